// round 1
// baseline (speedup 1.0000x reference)
#include <cuda_runtime.h>
#include <cstdint>
#include <cstdio>

// ---------------- problem constants ----------------
#define LSEQ   4096
#define HDIM   2048
#define NPROJ  12352      // QKVZ + BA
#define QKVZ_N 12288
#define KEY_DIM 2048
#define VAL_DIM 4096
#define NHK    16
#define NHV    32
#define DKC    128
#define DVC    128

// ---------------- scratch (device globals; no cudaMalloc allowed) -------------
__device__ float g_proj [(size_t)LSEQ * NPROJ];    // 202 MB
__device__ float g_q    [(size_t)LSEQ * KEY_DIM];  // l2norm'd * DK^-0.5, per HK head
__device__ float g_k    [(size_t)LSEQ * KEY_DIM];  // l2norm'd, per HK head
__device__ float g_v    [(size_t)LSEQ * VAL_DIM];
__device__ float g_gdec [(size_t)LSEQ * NHV];
__device__ float g_beta [(size_t)LSEQ * NHV];
__device__ float g_core [(size_t)LSEQ * VAL_DIM];
__device__ float g_gated[(size_t)LSEQ * VAL_DIM];

// ---------------- fp32 tiled GEMM: C[M,N] = A[M,K] @ B[K,N] -------------------
// BM=BN=128, BK=16, 256 threads, 8x8 per thread. M%128==0, K%16==0, N%4==0
// required; N edge handled by guards (N may not be a multiple of 128).
#define BM 128
#define BN 128
#define BK 16
#define TM 8
#define TN 8

__global__ __launch_bounds__(256) void sgemm_kernel(
    const float* __restrict__ A, const float* __restrict__ B,
    float* __restrict__ C, int M, int N, int K)
{
    __shared__ float As[BK][BM];
    __shared__ float Bs[BK][BN];

    const int tid = threadIdx.x;
    const int bm = blockIdx.y * BM;
    const int bn = blockIdx.x * BN;
    const int ty = tid >> 4;   // 0..15
    const int tx = tid & 15;   // 0..15

    float acc[TM][TN];
#pragma unroll
    for (int i = 0; i < TM; i++)
#pragma unroll
        for (int j = 0; j < TN; j++) acc[i][j] = 0.f;

    for (int k0 = 0; k0 < K; k0 += BK) {
        // load A tile (BM x BK) -> As transposed [BK][BM]
#pragma unroll
        for (int i = 0; i < 2; i++) {
            int f = tid + i * 256;          // 0..511 float4s
            int r = f >> 2;                 // row in tile
            int c4 = (f & 3) * 4;           // k offset
            float4 va = *(const float4*)&A[(size_t)(bm + r) * K + k0 + c4];
            As[c4 + 0][r] = va.x;
            As[c4 + 1][r] = va.y;
            As[c4 + 2][r] = va.z;
            As[c4 + 3][r] = va.w;
        }
        // load B tile (BK x BN)
#pragma unroll
        for (int i = 0; i < 2; i++) {
            int f = tid + i * 256;
            int r = f >> 5;                 // k row
            int c4 = (f & 31) * 4;          // col offset
            int col = bn + c4;
            float4 vb = make_float4(0.f, 0.f, 0.f, 0.f);
            if (col < N)                    // N%4==0 so col<N => col+3<N
                vb = *(const float4*)&B[(size_t)(k0 + r) * N + col];
            *(float4*)&Bs[r][c4] = vb;
        }
        __syncthreads();

#pragma unroll
        for (int kk = 0; kk < BK; kk++) {
            float a[TM], b[TN];
            *(float4*)&a[0] = *(const float4*)&As[kk][ty * TM];
            *(float4*)&a[4] = *(const float4*)&As[kk][ty * TM + 4];
            *(float4*)&b[0] = *(const float4*)&Bs[kk][tx * TN];
            *(float4*)&b[4] = *(const float4*)&Bs[kk][tx * TN + 4];
#pragma unroll
            for (int i = 0; i < TM; i++)
#pragma unroll
                for (int j = 0; j < TN; j++)
                    acc[i][j] += a[i] * b[j];
        }
        __syncthreads();
    }

#pragma unroll
    for (int i = 0; i < TM; i++) {
        size_t row = (size_t)(bm + ty * TM + i);
#pragma unroll
        for (int j = 0; j < TN; j += 4) {
            int col = bn + tx * TN + j;
            if (col < N) {
                float4 v = make_float4(acc[i][j], acc[i][j + 1], acc[i][j + 2], acc[i][j + 3]);
                *(float4*)&C[row * N + col] = v;
            }
        }
    }
}

// ---------------- conv(K=4) + silu + l2norm + gating prep ---------------------
// One CTA per sequence position l. Builds mixed_qkv row (8192) in smem from the
// permuted proj columns, applies depthwise conv + silu, computes per-head L2
// norms for q/k, writes q,k,v,g,beta.
__global__ __launch_bounds__(256) void prep_kernel(
    const float* __restrict__ proj, const float* __restrict__ conv_w,
    const float* __restrict__ A_log, const float* __restrict__ dt_bias,
    float* __restrict__ qo, float* __restrict__ ko, float* __restrict__ vo,
    float* __restrict__ go, float* __restrict__ bo)
{
    const int l = blockIdx.x;
    const int tid = threadIdx.x;
    __shared__ float buf[8192];
    __shared__ float inv[32];

    for (int f = tid; f < 8192; f += 256) {
        int col;
        if (f < 2048) {
            col = (f >> 7) * 768 + (f & 127);
        } else if (f < 4096) {
            int ff = f - 2048;
            col = (ff >> 7) * 768 + 128 + (ff & 127);
        } else {
            int ff = f - 4096;
            int hv = ff >> 7;
            col = (hv >> 1) * 768 + 256 + (hv & 1) * 128 + (ff & 127);
        }
        float4 w4 = *(const float4*)(conv_w + (size_t)f * 4);
        const float* pc = proj + col;
        float s;
        if (l >= 3) {
            s = w4.x * pc[(size_t)(l - 3) * NPROJ]
              + w4.y * pc[(size_t)(l - 2) * NPROJ]
              + w4.z * pc[(size_t)(l - 1) * NPROJ]
              + w4.w * pc[(size_t)l       * NPROJ];
        } else {
            s = w4.w * pc[(size_t)l * NPROJ];
            if (l >= 1) s += w4.z * pc[(size_t)(l - 1) * NPROJ];
            if (l >= 2) s += w4.y * pc[(size_t)(l - 2) * NPROJ];
        }
        // silu
        s = s / (1.f + __expf(-s));
        buf[f] = s;
    }
    __syncthreads();

    // 32 L2-norm groups (16 q heads, 16 k heads), 8 threads/group (same warp)
    {
        int grp = tid >> 3, sub = tid & 7;
        int base = (grp < 16) ? grp * 128 : 2048 + (grp - 16) * 128;
        float ss = 0.f;
#pragma unroll
        for (int i = 0; i < 16; i++) {
            float x = buf[base + sub * 16 + i];
            ss += x * x;
        }
        ss += __shfl_xor_sync(0xffffffffu, ss, 4);
        ss += __shfl_xor_sync(0xffffffffu, ss, 2);
        ss += __shfl_xor_sync(0xffffffffu, ss, 1);
        if (sub == 0) inv[grp] = rsqrtf(ss + 1e-6f);
    }
    __syncthreads();

    const float qscale = 0.08838834764831845f;  // 128^-0.5
    for (int f = tid; f < 2048; f += 256) {
        qo[(size_t)l * 2048 + f] = buf[f]        * inv[f >> 7] * qscale;
        ko[(size_t)l * 2048 + f] = buf[2048 + f] * inv[16 + (f >> 7)];
    }
    for (int f = tid; f < 4096; f += 256)
        vo[(size_t)l * 4096 + f] = buf[4096 + f];

    if (tid < 32) {
        const float* prow = proj + (size_t)l * NPROJ;
        int hv = tid, hk = hv >> 1, gg = hv & 1;
        float bb = prow[QKVZ_N + hk * 4 + gg];
        float aa = prow[QKVZ_N + hk * 4 + 2 + gg];
        bo[(size_t)l * 32 + hv] = 1.f / (1.f + __expf(-bb));
        float x = aa + dt_bias[hv];
        float sp = (x > 20.f) ? x : log1pf(__expf(x));
        go[(size_t)l * 32 + hv] = -__expf(A_log[hv]) * sp;
    }
}

// ---------------- sequential delta-rule scan ----------------------------------
// DV columns of the state are independent -> split each head across 4 CTAs of
// 32 columns. 128 threads/CTA: thread (w=tid>>5, lane=tid&31) owns the
// quarter-column S[dk in w*32..w*32+31][dv = split*32+lane] in 32 registers.
// Cross-warp smem reductions for k.S and q.S; double-buffered smem k/q staging
// with register prefetch of the next step to hide memory latency.
__global__ __launch_bounds__(128) void scan_kernel(
    const float* __restrict__ q, const float* __restrict__ k,
    const float* __restrict__ v, const float* __restrict__ g,
    const float* __restrict__ beta, float* __restrict__ core)
{
    const int hv = blockIdx.x >> 2;
    const int split = blockIdx.x & 3;
    const int hk = hv >> 1;
    const int tid = threadIdx.x;
    const int lane = tid & 31;
    const int w = tid >> 5;
    const int dv = split * 32 + lane;
    const int dkb = w * 32;

    __shared__ float ks[2][128];
    __shared__ float qs[2][128];
    __shared__ float red [2][4][32];
    __shared__ float red2[2][4][32];

    float S[32];
#pragma unroll
    for (int i = 0; i < 32; i++) S[i] = 0.f;

    const float* kbase = k + (size_t)hk * DKC;             // stride 2048 per t
    const float* qbase = q + (size_t)hk * DKC;
    const float* vbase = v + (size_t)hv * DVC + dv;        // stride 4096 per t
    const float* gbase = g + hv;                           // stride 32 per t
    const float* bbase = beta + hv;

    float4 kf = make_float4(0.f, 0.f, 0.f, 0.f);
    float4 qf = make_float4(0.f, 0.f, 0.f, 0.f);
    float vt, gt, bt;

    // prefetch t = 0
    if (tid < 32)       kf = *(const float4*)(kbase + (size_t)tid * 4);
    else if (tid < 64)  qf = *(const float4*)(qbase + (size_t)(tid - 32) * 4);
    vt = vbase[0];
    gt = gbase[0];
    bt = bbase[0];

    for (int t = 0; t < LSEQ; t++) {
        const int buf = t & 1;
        if (tid < 32)       *(float4*)&ks[buf][tid * 4] = kf;
        else if (tid < 64)  *(float4*)&qs[buf][(tid - 32) * 4] = qf;
        __syncthreads();

        // write previous step's output (red2[buf^1] is complete & visible now)
        if (t > 0 && w == 0) {
            float o = red2[buf ^ 1][0][lane] + red2[buf ^ 1][1][lane]
                    + red2[buf ^ 1][2][lane] + red2[buf ^ 1][3][lane];
            core[(size_t)(t - 1) * VAL_DIM + hv * DVC + dv] = o;
        }

        const float vt_c = vt, gt_c = gt, bt_c = bt;
        // prefetch t+1
        if (t + 1 < LSEQ) {
            const size_t tn = (size_t)(t + 1);
            if (tid < 32)       kf = *(const float4*)(kbase + tn * 2048 + tid * 4);
            else if (tid < 64)  qf = *(const float4*)(qbase + tn * 2048 + (tid - 32) * 4);
            vt = vbase[tn * 4096];
            gt = gbase[tn * 32];
            bt = bbase[tn * 32];
        }

        // pass 1: partial kv = k . S  (over this warp's dk quarter)
        float kr[32];
#pragma unroll
        for (int i = 0; i < 8; i++)
            *(float4*)&kr[i * 4] = *(const float4*)&ks[buf][dkb + i * 4];
        float a0 = 0.f, a1 = 0.f, a2 = 0.f, a3 = 0.f;
#pragma unroll
        for (int i = 0; i < 32; i += 4) {
            a0 += kr[i]     * S[i];
            a1 += kr[i + 1] * S[i + 1];
            a2 += kr[i + 2] * S[i + 2];
            a3 += kr[i + 3] * S[i + 3];
        }
        red[buf][w][lane] = (a0 + a1) + (a2 + a3);
        __syncthreads();

        const float kv = red[buf][0][lane] + red[buf][1][lane]
                       + red[buf][2][lane] + red[buf][3][lane];
        const float eg = __expf(gt_c);
        const float delta = (vt_c - eg * kv) * bt_c;

        // pass 2: S = eg*S + k*delta ; partial o = q . S
        float qr[32];
#pragma unroll
        for (int i = 0; i < 8; i++)
            *(float4*)&qr[i * 4] = *(const float4*)&qs[buf][dkb + i * 4];
        float o0 = 0.f, o1 = 0.f, o2 = 0.f, o3 = 0.f;
#pragma unroll
        for (int i = 0; i < 32; i += 4) {
            S[i]     = eg * S[i]     + kr[i]     * delta;  o0 += qr[i]     * S[i];
            S[i + 1] = eg * S[i + 1] + kr[i + 1] * delta;  o1 += qr[i + 1] * S[i + 1];
            S[i + 2] = eg * S[i + 2] + kr[i + 2] * delta;  o2 += qr[i + 2] * S[i + 2];
            S[i + 3] = eg * S[i + 3] + kr[i + 3] * delta;  o3 += qr[i + 3] * S[i + 3];
        }
        red2[buf][w][lane] = (o0 + o1) + (o2 + o3);
    }
    __syncthreads();
    if (w == 0) {
        const int buf = (LSEQ - 1) & 1;
        float o = red2[buf][0][lane] + red2[buf][1][lane]
                + red2[buf][2][lane] + red2[buf][3][lane];
        core[(size_t)(LSEQ - 1) * VAL_DIM + hv * DVC + dv] = o;
    }
}

// ---------------- RMS-ish norm + silu(z) gate ---------------------------------
// One CTA (128 threads) per (l, hv).
__global__ __launch_bounds__(128) void normgate_kernel(
    const float* __restrict__ core, const float* __restrict__ proj,
    const float* __restrict__ norm_w, float* __restrict__ gated)
{
    const int bx = blockIdx.x;          // l * 32 + hv
    const int l = bx >> 5;
    const int hv = bx & 31;
    const int d = threadIdx.x;

    float c = core[(size_t)bx * 128 + d];
    float ss = c * c;
#pragma unroll
    for (int o = 16; o > 0; o >>= 1)
        ss += __shfl_xor_sync(0xffffffffu, ss, o);
    __shared__ float r4[4];
    if ((d & 31) == 0) r4[d >> 5] = ss;
    __syncthreads();
    float var = (r4[0] + r4[1] + r4[2] + r4[3]) * (1.f / 128.f);

    int hk = hv >> 1, gg = hv & 1;
    float z = proj[(size_t)l * NPROJ + hk * 768 + 512 + gg * 128 + d];
    float sz = z / (1.f + __expf(-z));
    gated[(size_t)bx * 128 + d] = c * rsqrtf(var + 1e-6f) * norm_w[d] * sz;
}

// ---------------- launch ------------------------------------------------------
extern "C" void kernel_launch(void* const* d_in, const int* in_sizes, int n_in,
                              void* d_out, int out_size)
{
    const float* hidden     = (const float*)d_in[0];
    const float* in_proj_w  = (const float*)d_in[1];
    const float* conv_w     = (const float*)d_in[2];
    const float* A_log      = (const float*)d_in[3];
    const float* dt_bias    = (const float*)d_in[4];
    const float* norm_w     = (const float*)d_in[5];
    const float* out_proj_w = (const float*)d_in[6];
    float* out = (float*)d_out;

    float *p_proj, *p_q, *p_k, *p_v, *p_g, *p_b, *p_core, *p_gated;
    cudaGetSymbolAddress((void**)&p_proj,  g_proj);
    cudaGetSymbolAddress((void**)&p_q,     g_q);
    cudaGetSymbolAddress((void**)&p_k,     g_k);
    cudaGetSymbolAddress((void**)&p_v,     g_v);
    cudaGetSymbolAddress((void**)&p_g,     g_gdec);
    cudaGetSymbolAddress((void**)&p_b,     g_beta);
    cudaGetSymbolAddress((void**)&p_core,  g_core);
    cudaGetSymbolAddress((void**)&p_gated, g_gated);

    // 1) proj = hidden @ in_proj_w   (4096 x 12352, K=2048)
    dim3 grid1((NPROJ + BN - 1) / BN, LSEQ / BM);
    sgemm_kernel<<<grid1, 256>>>(hidden, in_proj_w, p_proj, LSEQ, NPROJ, HDIM);

    // 2) conv + silu + l2norm + gate params
    prep_kernel<<<LSEQ, 256>>>(p_proj, conv_w, A_log, dt_bias,
                               p_q, p_k, p_v, p_g, p_b);

    // 3) sequential scan (32 heads x 4 DV-splits)
    scan_kernel<<<NHV * 4, 128>>>(p_q, p_k, p_v, p_g, p_b, p_core);

    // 4) norm + silu(z) gate
    normgate_kernel<<<LSEQ * NHV, 128>>>(p_core, p_proj, norm_w, p_gated);

    // 5) out = gated @ out_proj_w   (4096 x 2048, K=4096)
    dim3 grid2((HDIM + BN - 1) / BN, LSEQ / BM);
    sgemm_kernel<<<grid2, 256>>>(p_gated, out_proj_w, out, LSEQ, HDIM, VAL_DIM);
}

// round 4
// speedup vs baseline: 1.7330x; 1.7330x over previous
#include <cuda_runtime.h>
#include <cuda_bf16.h>
#include <cstdint>

// ---------------- problem constants ----------------
#define LSEQ   4096
#define HDIM   2048
#define NPROJ  12352      // QKVZ + BA
#define QKVZ_N 12288
#define KEY_DIM 2048
#define VAL_DIM 4096
#define NHV    32
#define DKC    128
#define DVC    128
#define NPAD1  12416      // 97*128, padded N for GEMM1 B rows

// ---------------- scratch (device globals; no cudaMalloc allowed) -------------
__device__ float g_proj [(size_t)LSEQ * NPROJ];
__device__ float g_q    [(size_t)LSEQ * KEY_DIM];
__device__ float g_k    [(size_t)LSEQ * KEY_DIM];
__device__ float g_v    [(size_t)LSEQ * VAL_DIM];
__device__ float g_gdec [(size_t)LSEQ * NHV];
__device__ float g_beta [(size_t)LSEQ * NHV];
__device__ float g_core [(size_t)LSEQ * VAL_DIM];

__device__ __nv_bfloat16 g_hid_hi[(size_t)LSEQ * HDIM];
__device__ __nv_bfloat16 g_hid_lo[(size_t)LSEQ * HDIM];
__device__ __nv_bfloat16 g_w1_hi [(size_t)NPAD1 * HDIM];   // in_proj_w^T [N,K]
__device__ __nv_bfloat16 g_w1_lo [(size_t)NPAD1 * HDIM];
__device__ __nv_bfloat16 g_gat_hi[(size_t)LSEQ * VAL_DIM];
__device__ __nv_bfloat16 g_gat_lo[(size_t)LSEQ * VAL_DIM];
__device__ __nv_bfloat16 g_w2_hi [(size_t)HDIM * VAL_DIM]; // out_proj_w^T [N,K]
__device__ __nv_bfloat16 g_w2_lo [(size_t)HDIM * VAL_DIM];

// ---------------- helpers -------------------------------------------------------
__device__ __forceinline__ uint32_t smem_u32(const void* p) {
    uint32_t a;
    asm("{ .reg .u64 t; cvta.to.shared.u64 t, %1; cvt.u32.u64 %0, t; }"
        : "=r"(a) : "l"(p));
    return a;
}

// 64B-row swizzle: conflict-free for 16B-granular ldmatrix/cp.async on 64B rows
#define SW64(x) ((x) ^ (((x) >> 3) & 0x30))

__device__ __forceinline__ void cpa16(uint32_t s, const void* g) {
    asm volatile("cp.async.cg.shared.global [%0], [%1], 16;" :: "r"(s), "l"(g));
}
__device__ __forceinline__ void cpa_commit() {
    asm volatile("cp.async.commit_group;" ::: "memory");
}
__device__ __forceinline__ void cpa_wait1() {
    asm volatile("cp.async.wait_group 1;" ::: "memory");
}
__device__ __forceinline__ void cpa_wait0() {
    asm volatile("cp.async.wait_group 0;" ::: "memory");
}

__device__ __forceinline__ void ldsm4(uint32_t& r0, uint32_t& r1, uint32_t& r2,
                                      uint32_t& r3, uint32_t a) {
    asm volatile("ldmatrix.sync.aligned.m8n8.x4.shared.b16 {%0,%1,%2,%3}, [%4];"
                 : "=r"(r0), "=r"(r1), "=r"(r2), "=r"(r3) : "r"(a));
}

__device__ __forceinline__ void mma16816(float* c, const uint32_t* a,
                                         const uint32_t* b) {
    asm volatile(
        "mma.sync.aligned.m16n8k16.row.col.f32.bf16.bf16.f32 "
        "{%0,%1,%2,%3}, {%4,%5,%6,%7}, {%8,%9}, {%0,%1,%2,%3};"
        : "+f"(c[0]), "+f"(c[1]), "+f"(c[2]), "+f"(c[3])
        : "r"(a[0]), "r"(a[1]), "r"(a[2]), "r"(a[3]), "r"(b[0]), "r"(b[1]));
}

// ---------------- bf16x3 mma.sync GEMM ----------------------------------------
// C[M,N] fp32 = A[M,K] @ B[K,N]; A as hi/lo bf16 [M,K] K-major, B PRE-TRANSPOSED
// hi/lo bf16 [Npad,K] K-major. CTA tile 128x128, 8 warps of 32x64, K-chunk 32,
// cp.async double-buffered smem. 3 products: AhBh + AhBl + AlBh.
// stage = 4 tiles x 128 rows x 64B = 32KB; 2 stages = 64KB dynamic smem.
#define GSTAGE 32768
#define GEMM_SMEM (2 * GSTAGE)

__global__ __launch_bounds__(256, 1) void gemm_b3_kernel(
    const __nv_bfloat16* __restrict__ Ahi, const __nv_bfloat16* __restrict__ Alo,
    const __nv_bfloat16* __restrict__ Bhi, const __nv_bfloat16* __restrict__ Blo,
    float* __restrict__ C, int M, int N, int K)
{
    extern __shared__ char smem[];
    const uint32_t sb = smem_u32(smem);
    const int tid = threadIdx.x;
    const int wid = tid >> 5;
    const int lane = tid & 31;
    const int wm = wid >> 1;       // 0..3
    const int wn = wid & 1;        // 0..1
    const int bm = blockIdx.y * 128;
    const int bn = blockIdx.x * 128;

    // per-thread load mapping: 8 x 16B chunks per stage
    const int rowh = tid >> 2;     // 0..63
    const int kc = tid & 3;        // 16B chunk within 64B row
    const __nv_bfloat16* gp[4];
    gp[0] = Ahi + (size_t)bm * K;
    gp[1] = Alo + (size_t)bm * K;
    gp[2] = Bhi + (size_t)bn * K;
    gp[3] = Blo + (size_t)bn * K;

    float acc[2][8][4];
#pragma unroll
    for (int i = 0; i < 2; i++)
#pragma unroll
        for (int j = 0; j < 8; j++)
#pragma unroll
            for (int x = 0; x < 4; x++) acc[i][j][x] = 0.f;

    const int nk = K >> 5;

    // prologue: stage 0
    {
        const size_t k0 = 0;
#pragma unroll
        for (int j = 0; j < 8; j++) {
            const int tile = j >> 1;
            const int row = ((j & 1) << 6) + rowh;
            cpa16(sb + (tile << 13) + SW64((row << 6) + kc * 16),
                  gp[tile] + (size_t)row * K + k0 + kc * 8);
        }
        cpa_commit();
    }

    for (int kt = 0; kt < nk; ++kt) {
        if (kt + 1 < nk) {
            const size_t k0 = (size_t)(kt + 1) << 5;
            const uint32_t stb = sb + ((kt + 1) & 1) * GSTAGE;
#pragma unroll
            for (int j = 0; j < 8; j++) {
                const int tile = j >> 1;
                const int row = ((j & 1) << 6) + rowh;
                cpa16(stb + (tile << 13) + SW64((row << 6) + kc * 16),
                      gp[tile] + (size_t)row * K + k0 + kc * 8);
            }
            cpa_commit();
            cpa_wait1();
        } else {
            cpa_wait0();
        }
        __syncthreads();

        const uint32_t base = sb + (kt & 1) * GSTAGE;
#pragma unroll
        for (int prod = 0; prod < 3; prod++) {
            const uint32_t aB = base + ((prod == 2) ? 8192 : 0);
            const uint32_t bB = base + 16384 + ((prod == 1) ? 8192 : 0);
#pragma unroll
            for (int ks = 0; ks < 2; ks++) {
                uint32_t a[2][4];
#pragma unroll
                for (int t = 0; t < 2; t++) {
                    const uint32_t ad = aB + SW64(
                        ((wm * 32 + t * 16 + (lane & 15)) << 6)
                        + ks * 32 + ((lane >> 4) << 4));
                    ldsm4(a[t][0], a[t][1], a[t][2], a[t][3], ad);
                }
                uint32_t b[8][2];
#pragma unroll
                for (int p = 0; p < 4; p++) {
                    const uint32_t bd = bB + SW64(
                        ((wn * 64 + p * 16 + ((lane >> 4) << 3) + (lane & 7)) << 6)
                        + ks * 32 + (((lane >> 3) & 1) << 4));
                    ldsm4(b[2 * p][0], b[2 * p][1], b[2 * p + 1][0], b[2 * p + 1][1], bd);
                }
#pragma unroll
                for (int i = 0; i < 2; i++)
#pragma unroll
                    for (int j = 0; j < 8; j++)
                        mma16816(acc[i][j], a[i], b[j]);
            }
        }
        __syncthreads();
    }

    // epilogue
#pragma unroll
    for (int i = 0; i < 2; i++) {
        const int r0 = bm + wm * 32 + i * 16 + (lane >> 2);
#pragma unroll
        for (int j = 0; j < 8; j++) {
            const int col = bn + wn * 64 + j * 8 + (lane & 3) * 2;
            if (col < N) {
                *(float2*)&C[(size_t)r0 * N + col] =
                    make_float2(acc[i][j][0], acc[i][j][1]);
                *(float2*)&C[(size_t)(r0 + 8) * N + col] =
                    make_float2(acc[i][j][2], acc[i][j][3]);
            }
        }
    }
}

// ---------------- conversions --------------------------------------------------
__global__ __launch_bounds__(256) void conv_hl_kernel(
    const float* __restrict__ X, __nv_bfloat16* __restrict__ hi,
    __nv_bfloat16* __restrict__ lo, size_t n)
{
    size_t i = (size_t)blockIdx.x * 256 + threadIdx.x;
    if (i < n) {
        float x = X[i];
        __nv_bfloat16 h = __float2bfloat16(x);
        hi[i] = h;
        lo[i] = __float2bfloat16(x - __bfloat162float(h));
    }
}

// W[K, N] fp32 -> hi/lo bf16 [Npad, K] (transpose); rows n >= N are zero.
__global__ __launch_bounds__(256) void convT_kernel(
    const float* __restrict__ W, __nv_bfloat16* __restrict__ hi,
    __nv_bfloat16* __restrict__ lo, int K, int N)
{
    __shared__ float t[32][33];
    const int nb = blockIdx.x * 32;
    const int kb = blockIdx.y * 32;
    const int tx = threadIdx.x & 31;
    const int ty = threadIdx.x >> 5;
#pragma unroll
    for (int p = 0; p < 4; p++) {
        int r = ty + p * 8;                 // k row
        int n = nb + tx;
        t[r][tx] = (n < N) ? W[(size_t)(kb + r) * N + n] : 0.f;
    }
    __syncthreads();
#pragma unroll
    for (int p = 0; p < 4; p++) {
        int r = ty + p * 8;                 // output n row
        float x = t[tx][r];
        __nv_bfloat16 h = __float2bfloat16(x);
        __nv_bfloat16 l = __float2bfloat16(x - __bfloat162float(h));
        size_t o = (size_t)(nb + r) * K + kb + tx;
        hi[o] = h;
        lo[o] = l;
    }
}

// ---------------- conv(K=4) + silu + l2norm + gating prep ---------------------
__global__ __launch_bounds__(256) void prep_kernel(
    const float* __restrict__ proj, const float* __restrict__ conv_w,
    const float* __restrict__ A_log, const float* __restrict__ dt_bias,
    float* __restrict__ qo, float* __restrict__ ko, float* __restrict__ vo,
    float* __restrict__ go, float* __restrict__ bo)
{
    const int l = blockIdx.x;
    const int tid = threadIdx.x;
    __shared__ float buf[8192];
    __shared__ float inv[32];

    for (int f = tid; f < 8192; f += 256) {
        int col;
        if (f < 2048) {
            col = (f >> 7) * 768 + (f & 127);
        } else if (f < 4096) {
            int ff = f - 2048;
            col = (ff >> 7) * 768 + 128 + (ff & 127);
        } else {
            int ff = f - 4096;
            int hv = ff >> 7;
            col = (hv >> 1) * 768 + 256 + (hv & 1) * 128 + (ff & 127);
        }
        float4 w4 = *(const float4*)(conv_w + (size_t)f * 4);
        const float* pc = proj + col;
        float s;
        if (l >= 3) {
            s = w4.x * pc[(size_t)(l - 3) * NPROJ]
              + w4.y * pc[(size_t)(l - 2) * NPROJ]
              + w4.z * pc[(size_t)(l - 1) * NPROJ]
              + w4.w * pc[(size_t)l       * NPROJ];
        } else {
            s = w4.w * pc[(size_t)l * NPROJ];
            if (l >= 1) s += w4.z * pc[(size_t)(l - 1) * NPROJ];
            if (l >= 2) s += w4.y * pc[(size_t)(l - 2) * NPROJ];
        }
        s = s / (1.f + __expf(-s));
        buf[f] = s;
    }
    __syncthreads();

    {
        int grp = tid >> 3, sub = tid & 7;
        int base = (grp < 16) ? grp * 128 : 2048 + (grp - 16) * 128;
        float ss = 0.f;
#pragma unroll
        for (int i = 0; i < 16; i++) {
            float x = buf[base + sub * 16 + i];
            ss += x * x;
        }
        ss += __shfl_xor_sync(0xffffffffu, ss, 4);
        ss += __shfl_xor_sync(0xffffffffu, ss, 2);
        ss += __shfl_xor_sync(0xffffffffu, ss, 1);
        if (sub == 0) inv[grp] = rsqrtf(ss + 1e-6f);
    }
    __syncthreads();

    const float qscale = 0.08838834764831845f;  // 128^-0.5
    for (int f = tid; f < 2048; f += 256) {
        qo[(size_t)l * 2048 + f] = buf[f]        * inv[f >> 7] * qscale;
        ko[(size_t)l * 2048 + f] = buf[2048 + f] * inv[16 + (f >> 7)];
    }
    for (int f = tid; f < 4096; f += 256)
        vo[(size_t)l * 4096 + f] = buf[4096 + f];

    if (tid < 32) {
        const float* prow = proj + (size_t)l * NPROJ;
        int hv = tid, hk = hv >> 1, gg = hv & 1;
        float bb = prow[QKVZ_N + hk * 4 + gg];
        float aa = prow[QKVZ_N + hk * 4 + 2 + gg];
        bo[(size_t)l * 32 + hv] = 1.f / (1.f + __expf(-bb));
        float x = aa + dt_bias[hv];
        float sp = (x > 20.f) ? x : log1pf(__expf(x));
        go[(size_t)l * 32 + hv] = -__expf(A_log[hv]) * sp;
    }
}

// ---------------- sequential delta-rule scan ----------------------------------
__global__ __launch_bounds__(128) void scan_kernel(
    const float* __restrict__ q, const float* __restrict__ k,
    const float* __restrict__ v, const float* __restrict__ g,
    const float* __restrict__ beta, float* __restrict__ core)
{
    const int hv = blockIdx.x >> 2;
    const int split = blockIdx.x & 3;
    const int hk = hv >> 1;
    const int tid = threadIdx.x;
    const int lane = tid & 31;
    const int w = tid >> 5;
    const int dv = split * 32 + lane;
    const int dkb = w * 32;

    __shared__ float ks[2][128];
    __shared__ float qs[2][128];
    __shared__ float red [2][4][32];
    __shared__ float red2[2][4][32];

    float S[32];
#pragma unroll
    for (int i = 0; i < 32; i++) S[i] = 0.f;

    const float* kbase = k + (size_t)hk * DKC;
    const float* qbase = q + (size_t)hk * DKC;
    const float* vbase = v + (size_t)hv * DVC + dv;
    const float* gbase = g + hv;
    const float* bbase = beta + hv;

    float4 kf = make_float4(0.f, 0.f, 0.f, 0.f);
    float4 qf = make_float4(0.f, 0.f, 0.f, 0.f);
    float vt, gt, bt;

    if (tid < 32)       kf = *(const float4*)(kbase + (size_t)tid * 4);
    else if (tid < 64)  qf = *(const float4*)(qbase + (size_t)(tid - 32) * 4);
    vt = vbase[0];
    gt = gbase[0];
    bt = bbase[0];

    for (int t = 0; t < LSEQ; t++) {
        const int buf = t & 1;
        if (tid < 32)       *(float4*)&ks[buf][tid * 4] = kf;
        else if (tid < 64)  *(float4*)&qs[buf][(tid - 32) * 4] = qf;
        __syncthreads();

        if (t > 0 && w == 0) {
            float o = red2[buf ^ 1][0][lane] + red2[buf ^ 1][1][lane]
                    + red2[buf ^ 1][2][lane] + red2[buf ^ 1][3][lane];
            core[(size_t)(t - 1) * VAL_DIM + hv * DVC + dv] = o;
        }

        const float vt_c = vt, gt_c = gt, bt_c = bt;
        if (t + 1 < LSEQ) {
            const size_t tn = (size_t)(t + 1);
            if (tid < 32)       kf = *(const float4*)(kbase + tn * 2048 + tid * 4);
            else if (tid < 64)  qf = *(const float4*)(qbase + tn * 2048 + (tid - 32) * 4);
            vt = vbase[tn * 4096];
            gt = gbase[tn * 32];
            bt = bbase[tn * 32];
        }

        float kr[32];
#pragma unroll
        for (int i = 0; i < 8; i++)
            *(float4*)&kr[i * 4] = *(const float4*)&ks[buf][dkb + i * 4];
        float a0 = 0.f, a1 = 0.f, a2 = 0.f, a3 = 0.f;
#pragma unroll
        for (int i = 0; i < 32; i += 4) {
            a0 += kr[i]     * S[i];
            a1 += kr[i + 1] * S[i + 1];
            a2 += kr[i + 2] * S[i + 2];
            a3 += kr[i + 3] * S[i + 3];
        }
        red[buf][w][lane] = (a0 + a1) + (a2 + a3);
        __syncthreads();

        const float kv = red[buf][0][lane] + red[buf][1][lane]
                       + red[buf][2][lane] + red[buf][3][lane];
        const float eg = __expf(gt_c);
        const float delta = (vt_c - eg * kv) * bt_c;

        float qr[32];
#pragma unroll
        for (int i = 0; i < 8; i++)
            *(float4*)&qr[i * 4] = *(const float4*)&qs[buf][dkb + i * 4];
        float o0 = 0.f, o1 = 0.f, o2 = 0.f, o3 = 0.f;
#pragma unroll
        for (int i = 0; i < 32; i += 4) {
            S[i]     = eg * S[i]     + kr[i]     * delta;  o0 += qr[i]     * S[i];
            S[i + 1] = eg * S[i + 1] + kr[i + 1] * delta;  o1 += qr[i + 1] * S[i + 1];
            S[i + 2] = eg * S[i + 2] + kr[i + 2] * delta;  o2 += qr[i + 2] * S[i + 2];
            S[i + 3] = eg * S[i + 3] + kr[i + 3] * delta;  o3 += qr[i + 3] * S[i + 3];
        }
        red2[buf][w][lane] = (o0 + o1) + (o2 + o3);
    }
    __syncthreads();
    if (w == 0) {
        const int buf = (LSEQ - 1) & 1;
        float o = red2[buf][0][lane] + red2[buf][1][lane]
                + red2[buf][2][lane] + red2[buf][3][lane];
        core[(size_t)(LSEQ - 1) * VAL_DIM + hv * DVC + dv] = o;
    }
}

// ---------------- RMS-ish norm + silu(z) gate -> hi/lo bf16 -------------------
__global__ __launch_bounds__(128) void normgate_kernel(
    const float* __restrict__ core, const float* __restrict__ proj,
    const float* __restrict__ norm_w,
    __nv_bfloat16* __restrict__ ghi, __nv_bfloat16* __restrict__ glo)
{
    const int bx = blockIdx.x;          // l * 32 + hv
    const int l = bx >> 5;
    const int hv = bx & 31;
    const int d = threadIdx.x;

    float c = core[(size_t)bx * 128 + d];
    float ss = c * c;
#pragma unroll
    for (int o = 16; o > 0; o >>= 1)
        ss += __shfl_xor_sync(0xffffffffu, ss, o);
    __shared__ float r4[4];
    if ((d & 31) == 0) r4[d >> 5] = ss;
    __syncthreads();
    float var = (r4[0] + r4[1] + r4[2] + r4[3]) * (1.f / 128.f);

    int hk = hv >> 1, gg = hv & 1;
    float z = proj[(size_t)l * NPROJ + hk * 768 + 512 + gg * 128 + d];
    float sz = z / (1.f + __expf(-z));
    float val = c * rsqrtf(var + 1e-6f) * norm_w[d] * sz;

    __nv_bfloat16 h = __float2bfloat16(val);
    size_t idx = (size_t)bx * 128 + d;
    ghi[idx] = h;
    glo[idx] = __float2bfloat16(val - __bfloat162float(h));
}

// ---------------- launch ------------------------------------------------------
extern "C" void kernel_launch(void* const* d_in, const int* in_sizes, int n_in,
                              void* d_out, int out_size)
{
    const float* hidden     = (const float*)d_in[0];
    const float* in_proj_w  = (const float*)d_in[1];
    const float* conv_w     = (const float*)d_in[2];
    const float* A_log      = (const float*)d_in[3];
    const float* dt_bias    = (const float*)d_in[4];
    const float* norm_w     = (const float*)d_in[5];
    const float* out_proj_w = (const float*)d_in[6];
    float* out = (float*)d_out;

    float *p_proj, *p_q, *p_k, *p_v, *p_g, *p_b, *p_core;
    __nv_bfloat16 *p_hh, *p_hl, *p_w1h, *p_w1l, *p_gh, *p_gl, *p_w2h, *p_w2l;
    cudaGetSymbolAddress((void**)&p_proj, g_proj);
    cudaGetSymbolAddress((void**)&p_q,    g_q);
    cudaGetSymbolAddress((void**)&p_k,    g_k);
    cudaGetSymbolAddress((void**)&p_v,    g_v);
    cudaGetSymbolAddress((void**)&p_g,    g_gdec);
    cudaGetSymbolAddress((void**)&p_b,    g_beta);
    cudaGetSymbolAddress((void**)&p_core, g_core);
    cudaGetSymbolAddress((void**)&p_hh,   g_hid_hi);
    cudaGetSymbolAddress((void**)&p_hl,   g_hid_lo);
    cudaGetSymbolAddress((void**)&p_w1h,  g_w1_hi);
    cudaGetSymbolAddress((void**)&p_w1l,  g_w1_lo);
    cudaGetSymbolAddress((void**)&p_gh,   g_gat_hi);
    cudaGetSymbolAddress((void**)&p_gl,   g_gat_lo);
    cudaGetSymbolAddress((void**)&p_w2h,  g_w2_hi);
    cudaGetSymbolAddress((void**)&p_w2l,  g_w2_lo);

    cudaFuncSetAttribute(gemm_b3_kernel,
                         cudaFuncAttributeMaxDynamicSharedMemorySize, GEMM_SMEM);

    // operand conversions
    {
        size_t n = (size_t)LSEQ * HDIM;
        conv_hl_kernel<<<(unsigned)((n + 255) / 256), 256>>>(hidden, p_hh, p_hl, n);
    }
    convT_kernel<<<dim3(NPAD1 / 32, HDIM / 32), 256>>>(in_proj_w, p_w1h, p_w1l,
                                                       HDIM, NPROJ);
    convT_kernel<<<dim3(HDIM / 32, VAL_DIM / 32), 256>>>(out_proj_w, p_w2h, p_w2l,
                                                         VAL_DIM, HDIM);

    // 1) proj = hidden @ in_proj_w   (4096 x 12352, K=2048)
    gemm_b3_kernel<<<dim3(NPAD1 / 128, LSEQ / 128), 256, GEMM_SMEM>>>(
        p_hh, p_hl, p_w1h, p_w1l, p_proj, LSEQ, NPROJ, HDIM);

    // 2) conv + silu + l2norm + gate params
    prep_kernel<<<LSEQ, 256>>>(p_proj, conv_w, A_log, dt_bias,
                               p_q, p_k, p_v, p_g, p_b);

    // 3) sequential scan
    scan_kernel<<<NHV * 4, 128>>>(p_q, p_k, p_v, p_g, p_b, p_core);

    // 4) norm + gate -> bf16 hi/lo
    normgate_kernel<<<LSEQ * NHV, 128>>>(p_core, p_proj, norm_w, p_gh, p_gl);

    // 5) out = gated @ out_proj_w   (4096 x 2048, K=4096)
    gemm_b3_kernel<<<dim3(HDIM / 128, LSEQ / 128), 256, GEMM_SMEM>>>(
        p_gh, p_gl, p_w2h, p_w2l, out, LSEQ, HDIM, VAL_DIM);
}

// round 5
// speedup vs baseline: 1.7694x; 1.0210x over previous
#include <cuda_runtime.h>
#include <cuda_bf16.h>
#include <cstdint>

// ---------------- problem constants ----------------
#define LSEQ   4096
#define HDIM   2048
#define NPROJ  12352      // QKVZ + BA
#define QKVZ_N 12288
#define KEY_DIM 2048
#define VAL_DIM 4096
#define NHV    32
#define DKC    128
#define DVC    128
#define NPAD1  12416      // 97*128, padded N for GEMM1 B rows

// ---------------- scratch (device globals; no cudaMalloc allowed) -------------
__device__ float g_proj [(size_t)LSEQ * NPROJ];
__device__ float g_q    [(size_t)LSEQ * KEY_DIM];
__device__ float g_k    [(size_t)LSEQ * KEY_DIM];
__device__ float g_v    [(size_t)LSEQ * VAL_DIM];
__device__ float g_gdec [(size_t)LSEQ * NHV];
__device__ float g_beta [(size_t)LSEQ * NHV];
__device__ float g_core [(size_t)LSEQ * VAL_DIM];

__device__ __nv_bfloat16 g_hid_hi[(size_t)LSEQ * HDIM];
__device__ __nv_bfloat16 g_hid_lo[(size_t)LSEQ * HDIM];
__device__ __nv_bfloat16 g_w1_hi [(size_t)NPAD1 * HDIM];   // in_proj_w^T [N,K]
__device__ __nv_bfloat16 g_w1_lo [(size_t)NPAD1 * HDIM];
__device__ __nv_bfloat16 g_gat_hi[(size_t)LSEQ * VAL_DIM];
__device__ __nv_bfloat16 g_gat_lo[(size_t)LSEQ * VAL_DIM];
__device__ __nv_bfloat16 g_w2_hi [(size_t)HDIM * VAL_DIM]; // out_proj_w^T [N,K]
__device__ __nv_bfloat16 g_w2_lo [(size_t)HDIM * VAL_DIM];

// ---------------- helpers -------------------------------------------------------
__device__ __forceinline__ uint32_t smem_u32(const void* p) {
    uint32_t a;
    asm("{ .reg .u64 t; cvta.to.shared.u64 t, %1; cvt.u32.u64 %0, t; }"
        : "=r"(a) : "l"(p));
    return a;
}

// 64B-row swizzle: conflict-free for 16B-granular ldmatrix/cp.async on 64B rows
#define SW64(x) ((x) ^ (((x) >> 3) & 0x30))

__device__ __forceinline__ void cpa16(uint32_t s, const void* g) {
    asm volatile("cp.async.cg.shared.global [%0], [%1], 16;" :: "r"(s), "l"(g));
}
__device__ __forceinline__ void cpa_commit() {
    asm volatile("cp.async.commit_group;" ::: "memory");
}
__device__ __forceinline__ void cpa_wait2() {
    asm volatile("cp.async.wait_group 2;" ::: "memory");
}
__device__ __forceinline__ void cpa_wait1() {
    asm volatile("cp.async.wait_group 1;" ::: "memory");
}
__device__ __forceinline__ void cpa_wait0() {
    asm volatile("cp.async.wait_group 0;" ::: "memory");
}

__device__ __forceinline__ void ldsm4(uint32_t& r0, uint32_t& r1, uint32_t& r2,
                                      uint32_t& r3, uint32_t a) {
    asm volatile("ldmatrix.sync.aligned.m8n8.x4.shared.b16 {%0,%1,%2,%3}, [%4];"
                 : "=r"(r0), "=r"(r1), "=r"(r2), "=r"(r3) : "r"(a));
}

__device__ __forceinline__ void mma16816(float* c, const uint32_t* a,
                                         const uint32_t* b) {
    asm volatile(
        "mma.sync.aligned.m16n8k16.row.col.f32.bf16.bf16.f32 "
        "{%0,%1,%2,%3}, {%4,%5,%6,%7}, {%8,%9}, {%0,%1,%2,%3};"
        : "+f"(c[0]), "+f"(c[1]), "+f"(c[2]), "+f"(c[3])
        : "r"(a[0]), "r"(a[1]), "r"(a[2]), "r"(a[3]), "r"(b[0]), "r"(b[1]));
}

// ---------------- bf16x3 mma.sync GEMM ----------------------------------------
// C[M,N] fp32 = A[M,K] @ B[K,N]; A as hi/lo bf16 [M,K] K-major, B PRE-TRANSPOSED
// hi/lo bf16 [Npad,K] K-major. CTA tile 128x128, 8 warps of 32x64, K-chunk 32.
// 4-stage cp.async ring, ONE __syncthreads per chunk, fragments loaded once and
// reused across the 3 products (AhBh + AlBh + AhBl).
// stage = 4 tiles x 128 rows x 64B = 32KB; 4 stages = 128KB dynamic smem.
#define GSTAGE 32768
#define NSTAGE 4
#define GEMM_SMEM (NSTAGE * GSTAGE)

__global__ __launch_bounds__(256, 1) void gemm_b3_kernel(
    const __nv_bfloat16* __restrict__ Ahi, const __nv_bfloat16* __restrict__ Alo,
    const __nv_bfloat16* __restrict__ Bhi, const __nv_bfloat16* __restrict__ Blo,
    float* __restrict__ C, int M, int N, int K)
{
    extern __shared__ char smem[];
    const uint32_t sb = smem_u32(smem);
    const int tid = threadIdx.x;
    const int wid = tid >> 5;
    const int lane = tid & 31;
    const int wm = wid >> 1;       // 0..3
    const int wn = wid & 1;        // 0..1
    const int bm = blockIdx.y * 128;
    const int bn = blockIdx.x * 128;

    // per-thread load mapping: 8 x 16B chunks per stage
    const int rowh = tid >> 2;     // 0..63
    const int kc = tid & 3;        // 16B chunk within 64B row
    const __nv_bfloat16* gp[4];
    gp[0] = Ahi + (size_t)bm * K;
    gp[1] = Alo + (size_t)bm * K;
    gp[2] = Bhi + (size_t)bn * K;
    gp[3] = Blo + (size_t)bn * K;

    float acc[2][8][4];
#pragma unroll
    for (int i = 0; i < 2; i++)
#pragma unroll
        for (int j = 0; j < 8; j++)
#pragma unroll
            for (int x = 0; x < 4; x++) acc[i][j][x] = 0.f;

    const int nk = K >> 5;

    // precomputed ldmatrix address offsets (within a stage)
    uint32_t aoff[2][2], boff[4][2];   // [tile][ks]
#pragma unroll
    for (int t = 0; t < 2; t++)
#pragma unroll
        for (int ks = 0; ks < 2; ks++)
            aoff[t][ks] = SW64(((wm * 32 + t * 16 + (lane & 15)) << 6)
                               + ks * 32 + ((lane >> 4) << 4));
#pragma unroll
    for (int p = 0; p < 4; p++)
#pragma unroll
        for (int ks = 0; ks < 2; ks++)
            boff[p][ks] = SW64(((wn * 64 + p * 16 + ((lane >> 4) << 3) + (lane & 7)) << 6)
                               + ks * 32 + (((lane >> 3) & 1) << 4))
                          + 16384;

    // prologue: stages 0..2
#pragma unroll
    for (int s = 0; s < 3; s++) {
        const size_t k0 = (size_t)s << 5;
        const uint32_t stb = sb + s * GSTAGE;
#pragma unroll
        for (int j = 0; j < 8; j++) {
            const int tile = j >> 1;
            const int row = ((j & 1) << 6) + rowh;
            cpa16(stb + (tile << 13) + SW64((row << 6) + kc * 16),
                  gp[tile] + (size_t)row * K + k0 + kc * 8);
        }
        cpa_commit();
    }

    for (int kt = 0; kt < nk; ++kt) {
        // stage kt ready?
        if (kt < nk - 2)      cpa_wait2();
        else if (kt < nk - 1) cpa_wait1();
        else                  cpa_wait0();
        __syncthreads();

        // issue loads for stage kt+3 (buffer freed by iter kt-1; safe post-sync)
        if (kt + 3 < nk) {
            const size_t k0 = (size_t)(kt + 3) << 5;
            const uint32_t stb = sb + ((kt + 3) & (NSTAGE - 1)) * GSTAGE;
#pragma unroll
            for (int j = 0; j < 8; j++) {
                const int tile = j >> 1;
                const int row = ((j & 1) << 6) + rowh;
                cpa16(stb + (tile << 13) + SW64((row << 6) + kc * 16),
                      gp[tile] + (size_t)row * K + k0 + kc * 8);
            }
            cpa_commit();
        }

        const uint32_t base = sb + (kt & (NSTAGE - 1)) * GSTAGE;
#pragma unroll
        for (int ks = 0; ks < 2; ks++) {
            uint32_t ah[2][4], al[2][4], bh[8][2], bl[8][2];
#pragma unroll
            for (int t = 0; t < 2; t++) {
                ldsm4(ah[t][0], ah[t][1], ah[t][2], ah[t][3], base + aoff[t][ks]);
                ldsm4(al[t][0], al[t][1], al[t][2], al[t][3], base + 8192 + aoff[t][ks]);
            }
#pragma unroll
            for (int p = 0; p < 4; p++) {
                ldsm4(bh[2 * p][0], bh[2 * p][1], bh[2 * p + 1][0], bh[2 * p + 1][1],
                      base + boff[p][ks]);
                ldsm4(bl[2 * p][0], bl[2 * p][1], bl[2 * p + 1][0], bl[2 * p + 1][1],
                      base + 8192 + boff[p][ks]);
            }
#pragma unroll
            for (int i = 0; i < 2; i++)
#pragma unroll
                for (int j = 0; j < 8; j++)
                    mma16816(acc[i][j], ah[i], bh[j]);
#pragma unroll
            for (int i = 0; i < 2; i++)
#pragma unroll
                for (int j = 0; j < 8; j++)
                    mma16816(acc[i][j], al[i], bh[j]);
#pragma unroll
            for (int i = 0; i < 2; i++)
#pragma unroll
                for (int j = 0; j < 8; j++)
                    mma16816(acc[i][j], ah[i], bl[j]);
        }
    }

    // epilogue
#pragma unroll
    for (int i = 0; i < 2; i++) {
        const int r0 = bm + wm * 32 + i * 16 + (lane >> 2);
#pragma unroll
        for (int j = 0; j < 8; j++) {
            const int col = bn + wn * 64 + j * 8 + (lane & 3) * 2;
            if (col < N) {
                *(float2*)&C[(size_t)r0 * N + col] =
                    make_float2(acc[i][j][0], acc[i][j][1]);
                *(float2*)&C[(size_t)(r0 + 8) * N + col] =
                    make_float2(acc[i][j][2], acc[i][j][3]);
            }
        }
    }
}

// ---------------- conversions --------------------------------------------------
__global__ __launch_bounds__(256) void conv_hl_kernel(
    const float* __restrict__ X, __nv_bfloat16* __restrict__ hi,
    __nv_bfloat16* __restrict__ lo, size_t n)
{
    size_t i = (size_t)blockIdx.x * 256 + threadIdx.x;
    if (i < n) {
        float x = X[i];
        __nv_bfloat16 h = __float2bfloat16(x);
        hi[i] = h;
        lo[i] = __float2bfloat16(x - __bfloat162float(h));
    }
}

// W[K, N] fp32 -> hi/lo bf16 [Npad, K] (transpose); rows n >= N are zero.
__global__ __launch_bounds__(256) void convT_kernel(
    const float* __restrict__ W, __nv_bfloat16* __restrict__ hi,
    __nv_bfloat16* __restrict__ lo, int K, int N)
{
    __shared__ float t[32][33];
    const int nb = blockIdx.x * 32;
    const int kb = blockIdx.y * 32;
    const int tx = threadIdx.x & 31;
    const int ty = threadIdx.x >> 5;
#pragma unroll
    for (int p = 0; p < 4; p++) {
        int r = ty + p * 8;                 // k row
        int n = nb + tx;
        t[r][tx] = (n < N) ? W[(size_t)(kb + r) * N + n] : 0.f;
    }
    __syncthreads();
#pragma unroll
    for (int p = 0; p < 4; p++) {
        int r = ty + p * 8;                 // output n row
        float x = t[tx][r];
        __nv_bfloat16 h = __float2bfloat16(x);
        __nv_bfloat16 l = __float2bfloat16(x - __bfloat162float(h));
        size_t o = (size_t)(nb + r) * K + kb + tx;
        hi[o] = h;
        lo[o] = l;
    }
}

// ---------------- conv(K=4) + silu + l2norm + gating prep ---------------------
__global__ __launch_bounds__(256) void prep_kernel(
    const float* __restrict__ proj, const float* __restrict__ conv_w,
    const float* __restrict__ A_log, const float* __restrict__ dt_bias,
    float* __restrict__ qo, float* __restrict__ ko, float* __restrict__ vo,
    float* __restrict__ go, float* __restrict__ bo)
{
    const int l = blockIdx.x;
    const int tid = threadIdx.x;
    __shared__ float buf[8192];
    __shared__ float inv[32];

    for (int f = tid; f < 8192; f += 256) {
        int col;
        if (f < 2048) {
            col = (f >> 7) * 768 + (f & 127);
        } else if (f < 4096) {
            int ff = f - 2048;
            col = (ff >> 7) * 768 + 128 + (ff & 127);
        } else {
            int ff = f - 4096;
            int hv = ff >> 7;
            col = (hv >> 1) * 768 + 256 + (hv & 1) * 128 + (ff & 127);
        }
        float4 w4 = *(const float4*)(conv_w + (size_t)f * 4);
        const float* pc = proj + col;
        float s;
        if (l >= 3) {
            s = w4.x * pc[(size_t)(l - 3) * NPROJ]
              + w4.y * pc[(size_t)(l - 2) * NPROJ]
              + w4.z * pc[(size_t)(l - 1) * NPROJ]
              + w4.w * pc[(size_t)l       * NPROJ];
        } else {
            s = w4.w * pc[(size_t)l * NPROJ];
            if (l >= 1) s += w4.z * pc[(size_t)(l - 1) * NPROJ];
            if (l >= 2) s += w4.y * pc[(size_t)(l - 2) * NPROJ];
        }
        s = s / (1.f + __expf(-s));
        buf[f] = s;
    }
    __syncthreads();

    {
        int grp = tid >> 3, sub = tid & 7;
        int base = (grp < 16) ? grp * 128 : 2048 + (grp - 16) * 128;
        float ss = 0.f;
#pragma unroll
        for (int i = 0; i < 16; i++) {
            float x = buf[base + sub * 16 + i];
            ss += x * x;
        }
        ss += __shfl_xor_sync(0xffffffffu, ss, 4);
        ss += __shfl_xor_sync(0xffffffffu, ss, 2);
        ss += __shfl_xor_sync(0xffffffffu, ss, 1);
        if (sub == 0) inv[grp] = rsqrtf(ss + 1e-6f);
    }
    __syncthreads();

    const float qscale = 0.08838834764831845f;  // 128^-0.5
    for (int f = tid; f < 2048; f += 256) {
        qo[(size_t)l * 2048 + f] = buf[f]        * inv[f >> 7] * qscale;
        ko[(size_t)l * 2048 + f] = buf[2048 + f] * inv[16 + (f >> 7)];
    }
    for (int f = tid; f < 4096; f += 256)
        vo[(size_t)l * 4096 + f] = buf[4096 + f];

    if (tid < 32) {
        const float* prow = proj + (size_t)l * NPROJ;
        int hv = tid, hk = hv >> 1, gg = hv & 1;
        float bb = prow[QKVZ_N + hk * 4 + gg];
        float aa = prow[QKVZ_N + hk * 4 + 2 + gg];
        bo[(size_t)l * 32 + hv] = 1.f / (1.f + __expf(-bb));
        float x = aa + dt_bias[hv];
        float sp = (x > 20.f) ? x : log1pf(__expf(x));
        go[(size_t)l * 32 + hv] = -__expf(A_log[hv]) * sp;
    }
}

// ---------------- sequential delta-rule scan ----------------------------------
__global__ __launch_bounds__(128) void scan_kernel(
    const float* __restrict__ q, const float* __restrict__ k,
    const float* __restrict__ v, const float* __restrict__ g,
    const float* __restrict__ beta, float* __restrict__ core)
{
    const int hv = blockIdx.x >> 2;
    const int split = blockIdx.x & 3;
    const int hk = hv >> 1;
    const int tid = threadIdx.x;
    const int lane = tid & 31;
    const int w = tid >> 5;
    const int dv = split * 32 + lane;
    const int dkb = w * 32;

    __shared__ float ks[2][128];
    __shared__ float qs[2][128];
    __shared__ float red [2][4][32];
    __shared__ float red2[2][4][32];

    float S[32];
#pragma unroll
    for (int i = 0; i < 32; i++) S[i] = 0.f;

    const float* kbase = k + (size_t)hk * DKC;
    const float* qbase = q + (size_t)hk * DKC;
    const float* vbase = v + (size_t)hv * DVC + dv;
    const float* gbase = g + hv;
    const float* bbase = beta + hv;

    float4 kf = make_float4(0.f, 0.f, 0.f, 0.f);
    float4 qf = make_float4(0.f, 0.f, 0.f, 0.f);
    float vt, gt, bt;

    if (tid < 32)       kf = *(const float4*)(kbase + (size_t)tid * 4);
    else if (tid < 64)  qf = *(const float4*)(qbase + (size_t)(tid - 32) * 4);
    vt = vbase[0];
    gt = gbase[0];
    bt = bbase[0];

    for (int t = 0; t < LSEQ; t++) {
        const int buf = t & 1;
        if (tid < 32)       *(float4*)&ks[buf][tid * 4] = kf;
        else if (tid < 64)  *(float4*)&qs[buf][(tid - 32) * 4] = qf;
        __syncthreads();

        if (t > 0 && w == 0) {
            float o = red2[buf ^ 1][0][lane] + red2[buf ^ 1][1][lane]
                    + red2[buf ^ 1][2][lane] + red2[buf ^ 1][3][lane];
            core[(size_t)(t - 1) * VAL_DIM + hv * DVC + dv] = o;
        }

        const float vt_c = vt, gt_c = gt, bt_c = bt;
        if (t + 1 < LSEQ) {
            const size_t tn = (size_t)(t + 1);
            if (tid < 32)       kf = *(const float4*)(kbase + tn * 2048 + tid * 4);
            else if (tid < 64)  qf = *(const float4*)(qbase + tn * 2048 + (tid - 32) * 4);
            vt = vbase[tn * 4096];
            gt = gbase[tn * 32];
            bt = bbase[tn * 32];
        }

        float kr[32];
#pragma unroll
        for (int i = 0; i < 8; i++)
            *(float4*)&kr[i * 4] = *(const float4*)&ks[buf][dkb + i * 4];
        float a0 = 0.f, a1 = 0.f, a2 = 0.f, a3 = 0.f;
#pragma unroll
        for (int i = 0; i < 32; i += 4) {
            a0 += kr[i]     * S[i];
            a1 += kr[i + 1] * S[i + 1];
            a2 += kr[i + 2] * S[i + 2];
            a3 += kr[i + 3] * S[i + 3];
        }
        red[buf][w][lane] = (a0 + a1) + (a2 + a3);
        __syncthreads();

        const float kv = red[buf][0][lane] + red[buf][1][lane]
                       + red[buf][2][lane] + red[buf][3][lane];
        const float eg = __expf(gt_c);
        const float delta = (vt_c - eg * kv) * bt_c;

        float qr[32];
#pragma unroll
        for (int i = 0; i < 8; i++)
            *(float4*)&qr[i * 4] = *(const float4*)&qs[buf][dkb + i * 4];
        float o0 = 0.f, o1 = 0.f, o2 = 0.f, o3 = 0.f;
#pragma unroll
        for (int i = 0; i < 32; i += 4) {
            S[i]     = eg * S[i]     + kr[i]     * delta;  o0 += qr[i]     * S[i];
            S[i + 1] = eg * S[i + 1] + kr[i + 1] * delta;  o1 += qr[i + 1] * S[i + 1];
            S[i + 2] = eg * S[i + 2] + kr[i + 2] * delta;  o2 += qr[i + 2] * S[i + 2];
            S[i + 3] = eg * S[i + 3] + kr[i + 3] * delta;  o3 += qr[i + 3] * S[i + 3];
        }
        red2[buf][w][lane] = (o0 + o1) + (o2 + o3);
    }
    __syncthreads();
    if (w == 0) {
        const int buf = (LSEQ - 1) & 1;
        float o = red2[buf][0][lane] + red2[buf][1][lane]
                + red2[buf][2][lane] + red2[buf][3][lane];
        core[(size_t)(LSEQ - 1) * VAL_DIM + hv * DVC + dv] = o;
    }
}

// ---------------- RMS-ish norm + silu(z) gate -> hi/lo bf16 -------------------
__global__ __launch_bounds__(128) void normgate_kernel(
    const float* __restrict__ core, const float* __restrict__ proj,
    const float* __restrict__ norm_w,
    __nv_bfloat16* __restrict__ ghi, __nv_bfloat16* __restrict__ glo)
{
    const int bx = blockIdx.x;          // l * 32 + hv
    const int l = bx >> 5;
    const int hv = bx & 31;
    const int d = threadIdx.x;

    float c = core[(size_t)bx * 128 + d];
    float ss = c * c;
#pragma unroll
    for (int o = 16; o > 0; o >>= 1)
        ss += __shfl_xor_sync(0xffffffffu, ss, o);
    __shared__ float r4[4];
    if ((d & 31) == 0) r4[d >> 5] = ss;
    __syncthreads();
    float var = (r4[0] + r4[1] + r4[2] + r4[3]) * (1.f / 128.f);

    int hk = hv >> 1, gg = hv & 1;
    float z = proj[(size_t)l * NPROJ + hk * 768 + 512 + gg * 128 + d];
    float sz = z / (1.f + __expf(-z));
    float val = c * rsqrtf(var + 1e-6f) * norm_w[d] * sz;

    __nv_bfloat16 h = __float2bfloat16(val);
    size_t idx = (size_t)bx * 128 + d;
    ghi[idx] = h;
    glo[idx] = __float2bfloat16(val - __bfloat162float(h));
}

// ---------------- launch ------------------------------------------------------
extern "C" void kernel_launch(void* const* d_in, const int* in_sizes, int n_in,
                              void* d_out, int out_size)
{
    const float* hidden     = (const float*)d_in[0];
    const float* in_proj_w  = (const float*)d_in[1];
    const float* conv_w     = (const float*)d_in[2];
    const float* A_log      = (const float*)d_in[3];
    const float* dt_bias    = (const float*)d_in[4];
    const float* norm_w     = (const float*)d_in[5];
    const float* out_proj_w = (const float*)d_in[6];
    float* out = (float*)d_out;

    float *p_proj, *p_q, *p_k, *p_v, *p_g, *p_b, *p_core;
    __nv_bfloat16 *p_hh, *p_hl, *p_w1h, *p_w1l, *p_gh, *p_gl, *p_w2h, *p_w2l;
    cudaGetSymbolAddress((void**)&p_proj, g_proj);
    cudaGetSymbolAddress((void**)&p_q,    g_q);
    cudaGetSymbolAddress((void**)&p_k,    g_k);
    cudaGetSymbolAddress((void**)&p_v,    g_v);
    cudaGetSymbolAddress((void**)&p_g,    g_gdec);
    cudaGetSymbolAddress((void**)&p_b,    g_beta);
    cudaGetSymbolAddress((void**)&p_core, g_core);
    cudaGetSymbolAddress((void**)&p_hh,   g_hid_hi);
    cudaGetSymbolAddress((void**)&p_hl,   g_hid_lo);
    cudaGetSymbolAddress((void**)&p_w1h,  g_w1_hi);
    cudaGetSymbolAddress((void**)&p_w1l,  g_w1_lo);
    cudaGetSymbolAddress((void**)&p_gh,   g_gat_hi);
    cudaGetSymbolAddress((void**)&p_gl,   g_gat_lo);
    cudaGetSymbolAddress((void**)&p_w2h,  g_w2_hi);
    cudaGetSymbolAddress((void**)&p_w2l,  g_w2_lo);

    cudaFuncSetAttribute(gemm_b3_kernel,
                         cudaFuncAttributeMaxDynamicSharedMemorySize, GEMM_SMEM);

    // operand conversions
    {
        size_t n = (size_t)LSEQ * HDIM;
        conv_hl_kernel<<<(unsigned)((n + 255) / 256), 256>>>(hidden, p_hh, p_hl, n);
    }
    convT_kernel<<<dim3(NPAD1 / 32, HDIM / 32), 256>>>(in_proj_w, p_w1h, p_w1l,
                                                       HDIM, NPROJ);
    convT_kernel<<<dim3(HDIM / 32, VAL_DIM / 32), 256>>>(out_proj_w, p_w2h, p_w2l,
                                                         VAL_DIM, HDIM);

    // 1) proj = hidden @ in_proj_w   (4096 x 12352, K=2048)
    gemm_b3_kernel<<<dim3(NPAD1 / 128, LSEQ / 128), 256, GEMM_SMEM>>>(
        p_hh, p_hl, p_w1h, p_w1l, p_proj, LSEQ, NPROJ, HDIM);

    // 2) conv + silu + l2norm + gate params
    prep_kernel<<<LSEQ, 256>>>(p_proj, conv_w, A_log, dt_bias,
                               p_q, p_k, p_v, p_g, p_b);

    // 3) sequential scan
    scan_kernel<<<NHV * 4, 128>>>(p_q, p_k, p_v, p_g, p_b, p_core);

    // 4) norm + gate -> bf16 hi/lo
    normgate_kernel<<<LSEQ * NHV, 128>>>(p_core, p_proj, norm_w, p_gh, p_gl);

    // 5) out = gated @ out_proj_w   (4096 x 2048, K=4096)
    gemm_b3_kernel<<<dim3(HDIM / 128, LSEQ / 128), 256, GEMM_SMEM>>>(
        p_gh, p_gl, p_w2h, p_w2l, out, LSEQ, HDIM, VAL_DIM);
}

// round 6
// speedup vs baseline: 1.9085x; 1.0786x over previous
#include <cuda_runtime.h>
#include <cuda_bf16.h>
#include <cstdint>

// ---------------- problem constants ----------------
#define LSEQ   4096
#define HDIM   2048
#define NPROJ  12352      // QKVZ + BA
#define QKVZ_N 12288
#define KEY_DIM 2048
#define VAL_DIM 4096
#define NHV    32
#define DKC    128
#define DVC    128
#define NPAD1  12416      // 97*128, padded N for GEMM1 B rows

// ---------------- scratch (device globals; no cudaMalloc allowed) -------------
__device__ float g_proj [(size_t)LSEQ * NPROJ];
__device__ float g_q    [(size_t)LSEQ * KEY_DIM];
__device__ float g_k    [(size_t)LSEQ * KEY_DIM];
__device__ float g_v    [(size_t)LSEQ * VAL_DIM];
__device__ float g_gdec [(size_t)LSEQ * NHV];
__device__ float g_beta [(size_t)LSEQ * NHV];
__device__ float g_core [(size_t)LSEQ * VAL_DIM];

__device__ __nv_bfloat16 g_hid_hi[(size_t)LSEQ * HDIM];
__device__ __nv_bfloat16 g_hid_lo[(size_t)LSEQ * HDIM];
__device__ __nv_bfloat16 g_w1_hi [(size_t)NPAD1 * HDIM];   // in_proj_w^T [N,K]
__device__ __nv_bfloat16 g_w1_lo [(size_t)NPAD1 * HDIM];
__device__ __nv_bfloat16 g_gat_hi[(size_t)LSEQ * VAL_DIM];
__device__ __nv_bfloat16 g_gat_lo[(size_t)LSEQ * VAL_DIM];
__device__ __nv_bfloat16 g_w2_hi [(size_t)HDIM * VAL_DIM]; // out_proj_w^T [N,K]
__device__ __nv_bfloat16 g_w2_lo [(size_t)HDIM * VAL_DIM];

// ---------------- helpers -------------------------------------------------------
__device__ __forceinline__ uint32_t smem_u32(const void* p) {
    uint32_t a;
    asm("{ .reg .u64 t; cvta.to.shared.u64 t, %1; cvt.u32.u64 %0, t; }"
        : "=r"(a) : "l"(p));
    return a;
}

// 64B-row swizzle: conflict-free for 16B-granular ldmatrix/cp.async on 64B rows
#define SW64(x) ((x) ^ (((x) >> 3) & 0x30))

__device__ __forceinline__ void cpa16(uint32_t s, const void* g) {
    asm volatile("cp.async.cg.shared.global [%0], [%1], 16;" :: "r"(s), "l"(g));
}
__device__ __forceinline__ void cpa_commit() {
    asm volatile("cp.async.commit_group;" ::: "memory");
}
__device__ __forceinline__ void cpa_wait1() {
    asm volatile("cp.async.wait_group 1;" ::: "memory");
}
__device__ __forceinline__ void cpa_wait0() {
    asm volatile("cp.async.wait_group 0;" ::: "memory");
}

__device__ __forceinline__ void ldsm4(uint32_t& r0, uint32_t& r1, uint32_t& r2,
                                      uint32_t& r3, uint32_t a) {
    asm volatile("ldmatrix.sync.aligned.m8n8.x4.shared.b16 {%0,%1,%2,%3}, [%4];"
                 : "=r"(r0), "=r"(r1), "=r"(r2), "=r"(r3) : "r"(a));
}

__device__ __forceinline__ void mma16816(float* c, const uint32_t* a,
                                         const uint32_t* b) {
    asm volatile(
        "mma.sync.aligned.m16n8k16.row.col.f32.bf16.bf16.f32 "
        "{%0,%1,%2,%3}, {%4,%5,%6,%7}, {%8,%9}, {%0,%1,%2,%3};"
        : "+f"(c[0]), "+f"(c[1]), "+f"(c[2]), "+f"(c[3])
        : "r"(a[0]), "r"(a[1]), "r"(a[2]), "r"(a[3]), "r"(b[0]), "r"(b[1]));
}

// ---------------- bf16x3 mma.sync GEMM ----------------------------------------
// C[M,N] fp32 = A[M,K] @ B[K,N]; A as hi/lo bf16 [M,K] K-major, B PRE-TRANSPOSED
// hi/lo bf16 [Npad,K] K-major. CTA tile 128x128, 8 warps of 32x64, K-chunk 32.
// 3-stage cp.async ring (2 loads in flight), ONE __syncthreads per chunk,
// 2 CTAs/SM co-residency (96KB smem, <=128 regs). Bl fragments streamed to cut
// live registers. 3 products: AhBh + AlBh + AhBl.
#define GSTAGE 32768
#define NSTAGE 3
#define GEMM_SMEM (NSTAGE * GSTAGE)

__global__ __launch_bounds__(256, 2) void gemm_b3_kernel(
    const __nv_bfloat16* __restrict__ Ahi, const __nv_bfloat16* __restrict__ Alo,
    const __nv_bfloat16* __restrict__ Bhi, const __nv_bfloat16* __restrict__ Blo,
    float* __restrict__ C, int M, int N, int K)
{
    extern __shared__ char smem[];
    const uint32_t sb = smem_u32(smem);
    const int tid = threadIdx.x;
    const int wid = tid >> 5;
    const int lane = tid & 31;
    const int wm = wid >> 1;       // 0..3
    const int wn = wid & 1;        // 0..1
    const int bm = blockIdx.y * 128;
    const int bn = blockIdx.x * 128;

    // per-thread load mapping: 8 x 16B chunks per stage
    const int rowh = tid >> 2;     // 0..63
    const int kc = tid & 3;        // 16B chunk within 64B row
    const __nv_bfloat16* gp[4];
    gp[0] = Ahi + (size_t)bm * K;
    gp[1] = Alo + (size_t)bm * K;
    gp[2] = Bhi + (size_t)bn * K;
    gp[3] = Blo + (size_t)bn * K;

    float acc[2][8][4];
#pragma unroll
    for (int i = 0; i < 2; i++)
#pragma unroll
        for (int j = 0; j < 8; j++)
#pragma unroll
            for (int x = 0; x < 4; x++) acc[i][j][x] = 0.f;

    const int nk = K >> 5;

    // precomputed ldmatrix address offsets (within a stage)
    uint32_t aoff[2][2], boff[4][2];   // [tile][ks]
#pragma unroll
    for (int t = 0; t < 2; t++)
#pragma unroll
        for (int ks = 0; ks < 2; ks++)
            aoff[t][ks] = SW64(((wm * 32 + t * 16 + (lane & 15)) << 6)
                               + ks * 32 + ((lane >> 4) << 4));
#pragma unroll
    for (int p = 0; p < 4; p++)
#pragma unroll
        for (int ks = 0; ks < 2; ks++)
            boff[p][ks] = SW64(((wn * 64 + p * 16 + ((lane >> 4) << 3) + (lane & 7)) << 6)
                               + ks * 32 + (((lane >> 3) & 1) << 4))
                          + 16384;

    // prologue: stages 0..1
#pragma unroll
    for (int s = 0; s < 2; s++) {
        const size_t k0 = (size_t)s << 5;
        const uint32_t stb = sb + s * GSTAGE;
#pragma unroll
        for (int j = 0; j < 8; j++) {
            const int tile = j >> 1;
            const int row = ((j & 1) << 6) + rowh;
            cpa16(stb + (tile << 13) + SW64((row << 6) + kc * 16),
                  gp[tile] + (size_t)row * K + k0 + kc * 8);
        }
        cpa_commit();
    }

    int sc = 0;                     // current stage = kt % 3
    int sp = 2;                     // prefetch stage = (kt+2) % 3
    for (int kt = 0; kt < nk; ++kt) {
        // stage kt ready?  pending groups = {kt, kt+1} (except tail)
        if (kt < nk - 1) cpa_wait1();
        else             cpa_wait0();
        __syncthreads();

        // issue loads for stage kt+2 (buffer freed by iter kt-1; safe post-sync)
        if (kt + 2 < nk) {
            const size_t k0 = (size_t)(kt + 2) << 5;
            const uint32_t stb = sb + sp * GSTAGE;
#pragma unroll
            for (int j = 0; j < 8; j++) {
                const int tile = j >> 1;
                const int row = ((j & 1) << 6) + rowh;
                cpa16(stb + (tile << 13) + SW64((row << 6) + kc * 16),
                      gp[tile] + (size_t)row * K + k0 + kc * 8);
            }
            cpa_commit();
        }

        const uint32_t base = sb + sc * GSTAGE;
        if (++sc == NSTAGE) sc = 0;
        if (++sp == NSTAGE) sp = 0;

#pragma unroll
        for (int ks = 0; ks < 2; ks++) {
            uint32_t ah[2][4], al[2][4], bh[8][2];
#pragma unroll
            for (int t = 0; t < 2; t++) {
                ldsm4(ah[t][0], ah[t][1], ah[t][2], ah[t][3], base + aoff[t][ks]);
                ldsm4(al[t][0], al[t][1], al[t][2], al[t][3], base + 8192 + aoff[t][ks]);
            }
#pragma unroll
            for (int p = 0; p < 4; p++)
                ldsm4(bh[2 * p][0], bh[2 * p][1], bh[2 * p + 1][0], bh[2 * p + 1][1],
                      base + boff[p][ks]);
#pragma unroll
            for (int i = 0; i < 2; i++)
#pragma unroll
                for (int j = 0; j < 8; j++)
                    mma16816(acc[i][j], ah[i], bh[j]);
#pragma unroll
            for (int i = 0; i < 2; i++)
#pragma unroll
                for (int j = 0; j < 8; j++)
                    mma16816(acc[i][j], al[i], bh[j]);
            // streamed Bl: load a pair, use it, reuse registers
#pragma unroll
            for (int p = 0; p < 4; p++) {
                uint32_t bl0[2], bl1[2];
                ldsm4(bl0[0], bl0[1], bl1[0], bl1[1],
                      base + 8192 + boff[p][ks]);
                mma16816(acc[0][2 * p],     ah[0], bl0);
                mma16816(acc[1][2 * p],     ah[1], bl0);
                mma16816(acc[0][2 * p + 1], ah[0], bl1);
                mma16816(acc[1][2 * p + 1], ah[1], bl1);
            }
        }
    }

    // epilogue
#pragma unroll
    for (int i = 0; i < 2; i++) {
        const int r0 = bm + wm * 32 + i * 16 + (lane >> 2);
#pragma unroll
        for (int j = 0; j < 8; j++) {
            const int col = bn + wn * 64 + j * 8 + (lane & 3) * 2;
            if (col < N) {
                *(float2*)&C[(size_t)r0 * N + col] =
                    make_float2(acc[i][j][0], acc[i][j][1]);
                *(float2*)&C[(size_t)(r0 + 8) * N + col] =
                    make_float2(acc[i][j][2], acc[i][j][3]);
            }
        }
    }
}

// ---------------- conversions --------------------------------------------------
__global__ __launch_bounds__(256) void conv_hl_kernel(
    const float* __restrict__ X, __nv_bfloat16* __restrict__ hi,
    __nv_bfloat16* __restrict__ lo, size_t n)
{
    size_t i = (size_t)blockIdx.x * 256 + threadIdx.x;
    if (i < n) {
        float x = X[i];
        __nv_bfloat16 h = __float2bfloat16(x);
        hi[i] = h;
        lo[i] = __float2bfloat16(x - __bfloat162float(h));
    }
}

// W[K, N] fp32 -> hi/lo bf16 [Npad, K] (transpose); rows n >= N are zero.
__global__ __launch_bounds__(256) void convT_kernel(
    const float* __restrict__ W, __nv_bfloat16* __restrict__ hi,
    __nv_bfloat16* __restrict__ lo, int K, int N)
{
    __shared__ float t[32][33];
    const int nb = blockIdx.x * 32;
    const int kb = blockIdx.y * 32;
    const int tx = threadIdx.x & 31;
    const int ty = threadIdx.x >> 5;
#pragma unroll
    for (int p = 0; p < 4; p++) {
        int r = ty + p * 8;                 // k row
        int n = nb + tx;
        t[r][tx] = (n < N) ? W[(size_t)(kb + r) * N + n] : 0.f;
    }
    __syncthreads();
#pragma unroll
    for (int p = 0; p < 4; p++) {
        int r = ty + p * 8;                 // output n row
        float x = t[tx][r];
        __nv_bfloat16 h = __float2bfloat16(x);
        __nv_bfloat16 l = __float2bfloat16(x - __bfloat162float(h));
        size_t o = (size_t)(nb + r) * K + kb + tx;
        hi[o] = h;
        lo[o] = l;
    }
}

// ---------------- conv(K=4) + silu + l2norm + gating prep ---------------------
__global__ __launch_bounds__(256) void prep_kernel(
    const float* __restrict__ proj, const float* __restrict__ conv_w,
    const float* __restrict__ A_log, const float* __restrict__ dt_bias,
    float* __restrict__ qo, float* __restrict__ ko, float* __restrict__ vo,
    float* __restrict__ go, float* __restrict__ bo)
{
    const int l = blockIdx.x;
    const int tid = threadIdx.x;
    __shared__ float buf[8192];
    __shared__ float inv[32];

    for (int f = tid; f < 8192; f += 256) {
        int col;
        if (f < 2048) {
            col = (f >> 7) * 768 + (f & 127);
        } else if (f < 4096) {
            int ff = f - 2048;
            col = (ff >> 7) * 768 + 128 + (ff & 127);
        } else {
            int ff = f - 4096;
            int hv = ff >> 7;
            col = (hv >> 1) * 768 + 256 + (hv & 1) * 128 + (ff & 127);
        }
        float4 w4 = *(const float4*)(conv_w + (size_t)f * 4);
        const float* pc = proj + col;
        float s;
        if (l >= 3) {
            s = w4.x * pc[(size_t)(l - 3) * NPROJ]
              + w4.y * pc[(size_t)(l - 2) * NPROJ]
              + w4.z * pc[(size_t)(l - 1) * NPROJ]
              + w4.w * pc[(size_t)l       * NPROJ];
        } else {
            s = w4.w * pc[(size_t)l * NPROJ];
            if (l >= 1) s += w4.z * pc[(size_t)(l - 1) * NPROJ];
            if (l >= 2) s += w4.y * pc[(size_t)(l - 2) * NPROJ];
        }
        s = s / (1.f + __expf(-s));
        buf[f] = s;
    }
    __syncthreads();

    {
        int grp = tid >> 3, sub = tid & 7;
        int base = (grp < 16) ? grp * 128 : 2048 + (grp - 16) * 128;
        float ss = 0.f;
#pragma unroll
        for (int i = 0; i < 16; i++) {
            float x = buf[base + sub * 16 + i];
            ss += x * x;
        }
        ss += __shfl_xor_sync(0xffffffffu, ss, 4);
        ss += __shfl_xor_sync(0xffffffffu, ss, 2);
        ss += __shfl_xor_sync(0xffffffffu, ss, 1);
        if (sub == 0) inv[grp] = rsqrtf(ss + 1e-6f);
    }
    __syncthreads();

    const float qscale = 0.08838834764831845f;  // 128^-0.5
    for (int f = tid; f < 2048; f += 256) {
        qo[(size_t)l * 2048 + f] = buf[f]        * inv[f >> 7] * qscale;
        ko[(size_t)l * 2048 + f] = buf[2048 + f] * inv[16 + (f >> 7)];
    }
    for (int f = tid; f < 4096; f += 256)
        vo[(size_t)l * 4096 + f] = buf[4096 + f];

    if (tid < 32) {
        const float* prow = proj + (size_t)l * NPROJ;
        int hv = tid, hk = hv >> 1, gg = hv & 1;
        float bb = prow[QKVZ_N + hk * 4 + gg];
        float aa = prow[QKVZ_N + hk * 4 + 2 + gg];
        bo[(size_t)l * 32 + hv] = 1.f / (1.f + __expf(-bb));
        float x = aa + dt_bias[hv];
        float sp = (x > 20.f) ? x : log1pf(__expf(x));
        go[(size_t)l * 32 + hv] = -__expf(A_log[hv]) * sp;
    }
}

// ---------------- sequential delta-rule scan ----------------------------------
__global__ __launch_bounds__(128) void scan_kernel(
    const float* __restrict__ q, const float* __restrict__ k,
    const float* __restrict__ v, const float* __restrict__ g,
    const float* __restrict__ beta, float* __restrict__ core)
{
    const int hv = blockIdx.x >> 2;
    const int split = blockIdx.x & 3;
    const int hk = hv >> 1;
    const int tid = threadIdx.x;
    const int lane = tid & 31;
    const int w = tid >> 5;
    const int dv = split * 32 + lane;
    const int dkb = w * 32;

    __shared__ float ks[2][128];
    __shared__ float qs[2][128];
    __shared__ float red [2][4][32];
    __shared__ float red2[2][4][32];

    float S[32];
#pragma unroll
    for (int i = 0; i < 32; i++) S[i] = 0.f;

    const float* kbase = k + (size_t)hk * DKC;
    const float* qbase = q + (size_t)hk * DKC;
    const float* vbase = v + (size_t)hv * DVC + dv;
    const float* gbase = g + hv;
    const float* bbase = beta + hv;

    float4 kf = make_float4(0.f, 0.f, 0.f, 0.f);
    float4 qf = make_float4(0.f, 0.f, 0.f, 0.f);
    float vt, gt, bt;

    if (tid < 32)       kf = *(const float4*)(kbase + (size_t)tid * 4);
    else if (tid < 64)  qf = *(const float4*)(qbase + (size_t)(tid - 32) * 4);
    vt = vbase[0];
    gt = gbase[0];
    bt = bbase[0];

    for (int t = 0; t < LSEQ; t++) {
        const int buf = t & 1;
        if (tid < 32)       *(float4*)&ks[buf][tid * 4] = kf;
        else if (tid < 64)  *(float4*)&qs[buf][(tid - 32) * 4] = qf;
        __syncthreads();

        if (t > 0 && w == 0) {
            float o = red2[buf ^ 1][0][lane] + red2[buf ^ 1][1][lane]
                    + red2[buf ^ 1][2][lane] + red2[buf ^ 1][3][lane];
            core[(size_t)(t - 1) * VAL_DIM + hv * DVC + dv] = o;
        }

        const float vt_c = vt, gt_c = gt, bt_c = bt;
        if (t + 1 < LSEQ) {
            const size_t tn = (size_t)(t + 1);
            if (tid < 32)       kf = *(const float4*)(kbase + tn * 2048 + tid * 4);
            else if (tid < 64)  qf = *(const float4*)(qbase + tn * 2048 + (tid - 32) * 4);
            vt = vbase[tn * 4096];
            gt = gbase[tn * 32];
            bt = bbase[tn * 32];
        }

        float kr[32];
#pragma unroll
        for (int i = 0; i < 8; i++)
            *(float4*)&kr[i * 4] = *(const float4*)&ks[buf][dkb + i * 4];
        float a0 = 0.f, a1 = 0.f, a2 = 0.f, a3 = 0.f;
#pragma unroll
        for (int i = 0; i < 32; i += 4) {
            a0 += kr[i]     * S[i];
            a1 += kr[i + 1] * S[i + 1];
            a2 += kr[i + 2] * S[i + 2];
            a3 += kr[i + 3] * S[i + 3];
        }
        red[buf][w][lane] = (a0 + a1) + (a2 + a3);
        __syncthreads();

        const float kv = red[buf][0][lane] + red[buf][1][lane]
                       + red[buf][2][lane] + red[buf][3][lane];
        const float eg = __expf(gt_c);
        const float delta = (vt_c - eg * kv) * bt_c;

        float qr[32];
#pragma unroll
        for (int i = 0; i < 8; i++)
            *(float4*)&qr[i * 4] = *(const float4*)&qs[buf][dkb + i * 4];
        float o0 = 0.f, o1 = 0.f, o2 = 0.f, o3 = 0.f;
#pragma unroll
        for (int i = 0; i < 32; i += 4) {
            S[i]     = eg * S[i]     + kr[i]     * delta;  o0 += qr[i]     * S[i];
            S[i + 1] = eg * S[i + 1] + kr[i + 1] * delta;  o1 += qr[i + 1] * S[i + 1];
            S[i + 2] = eg * S[i + 2] + kr[i + 2] * delta;  o2 += qr[i + 2] * S[i + 2];
            S[i + 3] = eg * S[i + 3] + kr[i + 3] * delta;  o3 += qr[i + 3] * S[i + 3];
        }
        red2[buf][w][lane] = (o0 + o1) + (o2 + o3);
    }
    __syncthreads();
    if (w == 0) {
        const int buf = (LSEQ - 1) & 1;
        float o = red2[buf][0][lane] + red2[buf][1][lane]
                + red2[buf][2][lane] + red2[buf][3][lane];
        core[(size_t)(LSEQ - 1) * VAL_DIM + hv * DVC + dv] = o;
    }
}

// ---------------- RMS-ish norm + silu(z) gate -> hi/lo bf16 -------------------
__global__ __launch_bounds__(128) void normgate_kernel(
    const float* __restrict__ core, const float* __restrict__ proj,
    const float* __restrict__ norm_w,
    __nv_bfloat16* __restrict__ ghi, __nv_bfloat16* __restrict__ glo)
{
    const int bx = blockIdx.x;          // l * 32 + hv
    const int l = bx >> 5;
    const int hv = bx & 31;
    const int d = threadIdx.x;

    float c = core[(size_t)bx * 128 + d];
    float ss = c * c;
#pragma unroll
    for (int o = 16; o > 0; o >>= 1)
        ss += __shfl_xor_sync(0xffffffffu, ss, o);
    __shared__ float r4[4];
    if ((d & 31) == 0) r4[d >> 5] = ss;
    __syncthreads();
    float var = (r4[0] + r4[1] + r4[2] + r4[3]) * (1.f / 128.f);

    int hk = hv >> 1, gg = hv & 1;
    float z = proj[(size_t)l * NPROJ + hk * 768 + 512 + gg * 128 + d];
    float sz = z / (1.f + __expf(-z));
    float val = c * rsqrtf(var + 1e-6f) * norm_w[d] * sz;

    __nv_bfloat16 h = __float2bfloat16(val);
    size_t idx = (size_t)bx * 128 + d;
    ghi[idx] = h;
    glo[idx] = __float2bfloat16(val - __bfloat162float(h));
}

// ---------------- launch ------------------------------------------------------
extern "C" void kernel_launch(void* const* d_in, const int* in_sizes, int n_in,
                              void* d_out, int out_size)
{
    const float* hidden     = (const float*)d_in[0];
    const float* in_proj_w  = (const float*)d_in[1];
    const float* conv_w     = (const float*)d_in[2];
    const float* A_log      = (const float*)d_in[3];
    const float* dt_bias    = (const float*)d_in[4];
    const float* norm_w     = (const float*)d_in[5];
    const float* out_proj_w = (const float*)d_in[6];
    float* out = (float*)d_out;

    float *p_proj, *p_q, *p_k, *p_v, *p_g, *p_b, *p_core;
    __nv_bfloat16 *p_hh, *p_hl, *p_w1h, *p_w1l, *p_gh, *p_gl, *p_w2h, *p_w2l;
    cudaGetSymbolAddress((void**)&p_proj, g_proj);
    cudaGetSymbolAddress((void**)&p_q,    g_q);
    cudaGetSymbolAddress((void**)&p_k,    g_k);
    cudaGetSymbolAddress((void**)&p_v,    g_v);
    cudaGetSymbolAddress((void**)&p_g,    g_gdec);
    cudaGetSymbolAddress((void**)&p_b,    g_beta);
    cudaGetSymbolAddress((void**)&p_core, g_core);
    cudaGetSymbolAddress((void**)&p_hh,   g_hid_hi);
    cudaGetSymbolAddress((void**)&p_hl,   g_hid_lo);
    cudaGetSymbolAddress((void**)&p_w1h,  g_w1_hi);
    cudaGetSymbolAddress((void**)&p_w1l,  g_w1_lo);
    cudaGetSymbolAddress((void**)&p_gh,   g_gat_hi);
    cudaGetSymbolAddress((void**)&p_gl,   g_gat_lo);
    cudaGetSymbolAddress((void**)&p_w2h,  g_w2_hi);
    cudaGetSymbolAddress((void**)&p_w2l,  g_w2_lo);

    cudaFuncSetAttribute(gemm_b3_kernel,
                         cudaFuncAttributeMaxDynamicSharedMemorySize, GEMM_SMEM);

    // operand conversions
    {
        size_t n = (size_t)LSEQ * HDIM;
        conv_hl_kernel<<<(unsigned)((n + 255) / 256), 256>>>(hidden, p_hh, p_hl, n);
    }
    convT_kernel<<<dim3(NPAD1 / 32, HDIM / 32), 256>>>(in_proj_w, p_w1h, p_w1l,
                                                       HDIM, NPROJ);
    convT_kernel<<<dim3(HDIM / 32, VAL_DIM / 32), 256>>>(out_proj_w, p_w2h, p_w2l,
                                                         VAL_DIM, HDIM);

    // 1) proj = hidden @ in_proj_w   (4096 x 12352, K=2048)
    gemm_b3_kernel<<<dim3(NPAD1 / 128, LSEQ / 128), 256, GEMM_SMEM>>>(
        p_hh, p_hl, p_w1h, p_w1l, p_proj, LSEQ, NPROJ, HDIM);

    // 2) conv + silu + l2norm + gate params
    prep_kernel<<<LSEQ, 256>>>(p_proj, conv_w, A_log, dt_bias,
                               p_q, p_k, p_v, p_g, p_b);

    // 3) sequential scan
    scan_kernel<<<NHV * 4, 128>>>(p_q, p_k, p_v, p_g, p_b, p_core);

    // 4) norm + gate -> bf16 hi/lo
    normgate_kernel<<<LSEQ * NHV, 128>>>(p_core, p_proj, norm_w, p_gh, p_gl);

    // 5) out = gated @ out_proj_w   (4096 x 2048, K=4096)
    gemm_b3_kernel<<<dim3(HDIM / 128, LSEQ / 128), 256, GEMM_SMEM>>>(
        p_gh, p_gl, p_w2h, p_w2l, out, LSEQ, HDIM, VAL_DIM);
}

// round 7
// speedup vs baseline: 1.9092x; 1.0004x over previous
#include <cuda_runtime.h>
#include <cuda_bf16.h>
#include <cstdint>

// ---------------- problem constants ----------------
#define LSEQ   4096
#define HDIM   2048
#define NPROJ  12352      // QKVZ + BA
#define QKVZ_N 12288
#define KEY_DIM 2048
#define VAL_DIM 4096
#define NHV    32
#define DKC    128
#define DVC    128
#define NPAD1  12416      // 97*128, padded N for GEMM1 B rows

// ---------------- scratch (device globals; no cudaMalloc allowed) -------------
__device__ float g_proj [(size_t)LSEQ * NPROJ];
__device__ float g_q    [(size_t)LSEQ * KEY_DIM];
__device__ float g_k    [(size_t)LSEQ * KEY_DIM];
__device__ float g_v    [(size_t)LSEQ * VAL_DIM];
__device__ float g_gdec [(size_t)LSEQ * NHV];
__device__ float g_beta [(size_t)LSEQ * NHV];
__device__ float g_core [(size_t)LSEQ * VAL_DIM];

__device__ __nv_bfloat16 g_hid_hi[(size_t)LSEQ * HDIM];
__device__ __nv_bfloat16 g_hid_lo[(size_t)LSEQ * HDIM];
__device__ __nv_bfloat16 g_w1_hi [(size_t)NPAD1 * HDIM];   // in_proj_w^T [N,K]
__device__ __nv_bfloat16 g_w1_lo [(size_t)NPAD1 * HDIM];
__device__ __nv_bfloat16 g_gat_hi[(size_t)LSEQ * VAL_DIM];
__device__ __nv_bfloat16 g_gat_lo[(size_t)LSEQ * VAL_DIM];
__device__ __nv_bfloat16 g_w2_hi [(size_t)HDIM * VAL_DIM]; // out_proj_w^T [N,K]
__device__ __nv_bfloat16 g_w2_lo [(size_t)HDIM * VAL_DIM];

// ---------------- helpers -------------------------------------------------------
__device__ __forceinline__ uint32_t smem_u32(const void* p) {
    uint32_t a;
    asm("{ .reg .u64 t; cvta.to.shared.u64 t, %1; cvt.u32.u64 %0, t; }"
        : "=r"(a) : "l"(p));
    return a;
}

// 64B-row swizzle: conflict-free for 16B-granular ldmatrix/cp.async on 64B rows
#define SW64(x) ((x) ^ (((x) >> 3) & 0x30))

__device__ __forceinline__ void cpa16(uint32_t s, const void* g) {
    asm volatile("cp.async.cg.shared.global [%0], [%1], 16;" :: "r"(s), "l"(g));
}
__device__ __forceinline__ void cpa_commit() {
    asm volatile("cp.async.commit_group;" ::: "memory");
}
__device__ __forceinline__ void cpa_wait1() {
    asm volatile("cp.async.wait_group 1;" ::: "memory");
}
__device__ __forceinline__ void cpa_wait0() {
    asm volatile("cp.async.wait_group 0;" ::: "memory");
}

__device__ __forceinline__ void ldsm4(uint32_t& r0, uint32_t& r1, uint32_t& r2,
                                      uint32_t& r3, uint32_t a) {
    asm volatile("ldmatrix.sync.aligned.m8n8.x4.shared.b16 {%0,%1,%2,%3}, [%4];"
                 : "=r"(r0), "=r"(r1), "=r"(r2), "=r"(r3) : "r"(a));
}

__device__ __forceinline__ void mma16816(float* c, const uint32_t* a,
                                         const uint32_t* b) {
    asm volatile(
        "mma.sync.aligned.m16n8k16.row.col.f32.bf16.bf16.f32 "
        "{%0,%1,%2,%3}, {%4,%5,%6,%7}, {%8,%9}, {%0,%1,%2,%3};"
        : "+f"(c[0]), "+f"(c[1]), "+f"(c[2]), "+f"(c[3])
        : "r"(a[0]), "r"(a[1]), "r"(a[2]), "r"(a[3]), "r"(b[0]), "r"(b[1]));
}

// ---------------- bf16x3 mma.sync GEMM (unchanged from R6) ---------------------
#define GSTAGE 32768
#define NSTAGE 3
#define GEMM_SMEM (NSTAGE * GSTAGE)

__global__ __launch_bounds__(256, 2) void gemm_b3_kernel(
    const __nv_bfloat16* __restrict__ Ahi, const __nv_bfloat16* __restrict__ Alo,
    const __nv_bfloat16* __restrict__ Bhi, const __nv_bfloat16* __restrict__ Blo,
    float* __restrict__ C, int M, int N, int K)
{
    extern __shared__ char smem[];
    const uint32_t sb = smem_u32(smem);
    const int tid = threadIdx.x;
    const int wid = tid >> 5;
    const int lane = tid & 31;
    const int wm = wid >> 1;       // 0..3
    const int wn = wid & 1;        // 0..1
    const int bm = blockIdx.y * 128;
    const int bn = blockIdx.x * 128;

    const int rowh = tid >> 2;     // 0..63
    const int kc = tid & 3;        // 16B chunk within 64B row
    const __nv_bfloat16* gp[4];
    gp[0] = Ahi + (size_t)bm * K;
    gp[1] = Alo + (size_t)bm * K;
    gp[2] = Bhi + (size_t)bn * K;
    gp[3] = Blo + (size_t)bn * K;

    float acc[2][8][4];
#pragma unroll
    for (int i = 0; i < 2; i++)
#pragma unroll
        for (int j = 0; j < 8; j++)
#pragma unroll
            for (int x = 0; x < 4; x++) acc[i][j][x] = 0.f;

    const int nk = K >> 5;

    uint32_t aoff[2][2], boff[4][2];   // [tile][ks]
#pragma unroll
    for (int t = 0; t < 2; t++)
#pragma unroll
        for (int ks = 0; ks < 2; ks++)
            aoff[t][ks] = SW64(((wm * 32 + t * 16 + (lane & 15)) << 6)
                               + ks * 32 + ((lane >> 4) << 4));
#pragma unroll
    for (int p = 0; p < 4; p++)
#pragma unroll
        for (int ks = 0; ks < 2; ks++)
            boff[p][ks] = SW64(((wn * 64 + p * 16 + ((lane >> 4) << 3) + (lane & 7)) << 6)
                               + ks * 32 + (((lane >> 3) & 1) << 4))
                          + 16384;

#pragma unroll
    for (int s = 0; s < 2; s++) {
        const size_t k0 = (size_t)s << 5;
        const uint32_t stb = sb + s * GSTAGE;
#pragma unroll
        for (int j = 0; j < 8; j++) {
            const int tile = j >> 1;
            const int row = ((j & 1) << 6) + rowh;
            cpa16(stb + (tile << 13) + SW64((row << 6) + kc * 16),
                  gp[tile] + (size_t)row * K + k0 + kc * 8);
        }
        cpa_commit();
    }

    int sc = 0;
    int sp = 2;
    for (int kt = 0; kt < nk; ++kt) {
        if (kt < nk - 1) cpa_wait1();
        else             cpa_wait0();
        __syncthreads();

        if (kt + 2 < nk) {
            const size_t k0 = (size_t)(kt + 2) << 5;
            const uint32_t stb = sb + sp * GSTAGE;
#pragma unroll
            for (int j = 0; j < 8; j++) {
                const int tile = j >> 1;
                const int row = ((j & 1) << 6) + rowh;
                cpa16(stb + (tile << 13) + SW64((row << 6) + kc * 16),
                      gp[tile] + (size_t)row * K + k0 + kc * 8);
            }
            cpa_commit();
        }

        const uint32_t base = sb + sc * GSTAGE;
        if (++sc == NSTAGE) sc = 0;
        if (++sp == NSTAGE) sp = 0;

#pragma unroll
        for (int ks = 0; ks < 2; ks++) {
            uint32_t ah[2][4], al[2][4], bh[8][2];
#pragma unroll
            for (int t = 0; t < 2; t++) {
                ldsm4(ah[t][0], ah[t][1], ah[t][2], ah[t][3], base + aoff[t][ks]);
                ldsm4(al[t][0], al[t][1], al[t][2], al[t][3], base + 8192 + aoff[t][ks]);
            }
#pragma unroll
            for (int p = 0; p < 4; p++)
                ldsm4(bh[2 * p][0], bh[2 * p][1], bh[2 * p + 1][0], bh[2 * p + 1][1],
                      base + boff[p][ks]);
#pragma unroll
            for (int i = 0; i < 2; i++)
#pragma unroll
                for (int j = 0; j < 8; j++)
                    mma16816(acc[i][j], ah[i], bh[j]);
#pragma unroll
            for (int i = 0; i < 2; i++)
#pragma unroll
                for (int j = 0; j < 8; j++)
                    mma16816(acc[i][j], al[i], bh[j]);
#pragma unroll
            for (int p = 0; p < 4; p++) {
                uint32_t bl0[2], bl1[2];
                ldsm4(bl0[0], bl0[1], bl1[0], bl1[1],
                      base + 8192 + boff[p][ks]);
                mma16816(acc[0][2 * p],     ah[0], bl0);
                mma16816(acc[1][2 * p],     ah[1], bl0);
                mma16816(acc[0][2 * p + 1], ah[0], bl1);
                mma16816(acc[1][2 * p + 1], ah[1], bl1);
            }
        }
    }

#pragma unroll
    for (int i = 0; i < 2; i++) {
        const int r0 = bm + wm * 32 + i * 16 + (lane >> 2);
#pragma unroll
        for (int j = 0; j < 8; j++) {
            const int col = bn + wn * 64 + j * 8 + (lane & 3) * 2;
            if (col < N) {
                *(float2*)&C[(size_t)r0 * N + col] =
                    make_float2(acc[i][j][0], acc[i][j][1]);
                *(float2*)&C[(size_t)(r0 + 8) * N + col] =
                    make_float2(acc[i][j][2], acc[i][j][3]);
            }
        }
    }
}

// ---------------- conversions --------------------------------------------------
__global__ __launch_bounds__(256) void conv_hl_kernel(
    const float* __restrict__ X, __nv_bfloat16* __restrict__ hi,
    __nv_bfloat16* __restrict__ lo, size_t n)
{
    size_t i = (size_t)blockIdx.x * 256 + threadIdx.x;
    if (i < n) {
        float x = X[i];
        __nv_bfloat16 h = __float2bfloat16(x);
        hi[i] = h;
        lo[i] = __float2bfloat16(x - __bfloat162float(h));
    }
}

// W[K, N] fp32 -> hi/lo bf16 [Npad, K] (transpose); rows n >= N are zero.
__global__ __launch_bounds__(256) void convT_kernel(
    const float* __restrict__ W, __nv_bfloat16* __restrict__ hi,
    __nv_bfloat16* __restrict__ lo, int K, int N)
{
    __shared__ float t[32][33];
    const int nb = blockIdx.x * 32;
    const int kb = blockIdx.y * 32;
    const int tx = threadIdx.x & 31;
    const int ty = threadIdx.x >> 5;
#pragma unroll
    for (int p = 0; p < 4; p++) {
        int r = ty + p * 8;                 // k row
        int n = nb + tx;
        t[r][tx] = (n < N) ? W[(size_t)(kb + r) * N + n] : 0.f;
    }
    __syncthreads();
#pragma unroll
    for (int p = 0; p < 4; p++) {
        int r = ty + p * 8;                 // output n row
        float x = t[tx][r];
        __nv_bfloat16 h = __float2bfloat16(x);
        __nv_bfloat16 l = __float2bfloat16(x - __bfloat162float(h));
        size_t o = (size_t)(nb + r) * K + kb + tx;
        hi[o] = h;
        lo[o] = l;
    }
}

// ---------------- conv(K=4) + silu + l2norm + gating prep ---------------------
__global__ __launch_bounds__(256) void prep_kernel(
    const float* __restrict__ proj, const float* __restrict__ conv_w,
    const float* __restrict__ A_log, const float* __restrict__ dt_bias,
    float* __restrict__ qo, float* __restrict__ ko, float* __restrict__ vo,
    float* __restrict__ go, float* __restrict__ bo)
{
    const int l = blockIdx.x;
    const int tid = threadIdx.x;
    __shared__ float buf[8192];
    __shared__ float inv[32];

    for (int f = tid; f < 8192; f += 256) {
        int col;
        if (f < 2048) {
            col = (f >> 7) * 768 + (f & 127);
        } else if (f < 4096) {
            int ff = f - 2048;
            col = (ff >> 7) * 768 + 128 + (ff & 127);
        } else {
            int ff = f - 4096;
            int hv = ff >> 7;
            col = (hv >> 1) * 768 + 256 + (hv & 1) * 128 + (ff & 127);
        }
        float4 w4 = *(const float4*)(conv_w + (size_t)f * 4);
        const float* pc = proj + col;
        float s;
        if (l >= 3) {
            s = w4.x * pc[(size_t)(l - 3) * NPROJ]
              + w4.y * pc[(size_t)(l - 2) * NPROJ]
              + w4.z * pc[(size_t)(l - 1) * NPROJ]
              + w4.w * pc[(size_t)l       * NPROJ];
        } else {
            s = w4.w * pc[(size_t)l * NPROJ];
            if (l >= 1) s += w4.z * pc[(size_t)(l - 1) * NPROJ];
            if (l >= 2) s += w4.y * pc[(size_t)(l - 2) * NPROJ];
        }
        s = s / (1.f + __expf(-s));
        buf[f] = s;
    }
    __syncthreads();

    {
        int grp = tid >> 3, sub = tid & 7;
        int base = (grp < 16) ? grp * 128 : 2048 + (grp - 16) * 128;
        float ss = 0.f;
#pragma unroll
        for (int i = 0; i < 16; i++) {
            float x = buf[base + sub * 16 + i];
            ss += x * x;
        }
        ss += __shfl_xor_sync(0xffffffffu, ss, 4);
        ss += __shfl_xor_sync(0xffffffffu, ss, 2);
        ss += __shfl_xor_sync(0xffffffffu, ss, 1);
        if (sub == 0) inv[grp] = rsqrtf(ss + 1e-6f);
    }
    __syncthreads();

    const float qscale = 0.08838834764831845f;  // 128^-0.5
    for (int f = tid; f < 2048; f += 256) {
        qo[(size_t)l * 2048 + f] = buf[f]        * inv[f >> 7] * qscale;
        ko[(size_t)l * 2048 + f] = buf[2048 + f] * inv[16 + (f >> 7)];
    }
    for (int f = tid; f < 4096; f += 256)
        vo[(size_t)l * 4096 + f] = buf[4096 + f];

    if (tid < 32) {
        const float* prow = proj + (size_t)l * NPROJ;
        int hv = tid, hk = hv >> 1, gg = hv & 1;
        float bb = prow[QKVZ_N + hk * 4 + gg];
        float aa = prow[QKVZ_N + hk * 4 + 2 + gg];
        bo[(size_t)l * 32 + hv] = 1.f / (1.f + __expf(-bb));
        float x = aa + dt_bias[hv];
        float sp = (x > 20.f) ? x : log1pf(__expf(x));
        go[(size_t)l * 32 + hv] = -__expf(A_log[hv]) * sp;
    }
}

// ---------------- warp-autonomous delta-rule scan ------------------------------
// One warp per (hv, 8-column dv octet): 32 hv * 16 octets = 512 warps.
// lane = dkq*8 + dvi; each lane owns S[dk = dkq*32 .. +32)[dv = octet*8+dvi] in
// 32 registers. Reductions over dk are 2 butterfly shuffles (xor 8, xor 16).
// No __syncthreads, no smem. k/q/v/g/b register double-buffered (unroll x2).
struct ScanBuf {
    float4 k[8];
    float4 q[8];
    float  v, g, b;
};

__device__ __forceinline__ void scan_load(
    ScanBuf& s, const float* kp, const float* qp, const float* vp,
    const float* gp, const float* bp, int t)
{
    const float* kr = kp + (size_t)t * KEY_DIM;
    const float* qr = qp + (size_t)t * KEY_DIM;
#pragma unroll
    for (int j = 0; j < 8; j++) {
        s.k[j] = *(const float4*)(kr + j * 4);
        s.q[j] = *(const float4*)(qr + j * 4);
    }
    s.v = vp[(size_t)t * VAL_DIM];
    s.g = gp[(size_t)t * NHV];
    s.b = bp[(size_t)t * NHV];
}

__device__ __forceinline__ void scan_step(
    const ScanBuf& sbuf, float* S, float* outp, int write_lane)
{
    // kv = k . S (local) -> butterfly over dkq
    float a0 = 0.f, a1 = 0.f, a2 = 0.f, a3 = 0.f;
#pragma unroll
    for (int j = 0; j < 8; j++) {
        a0 += sbuf.k[j].x * S[4 * j];
        a1 += sbuf.k[j].y * S[4 * j + 1];
        a2 += sbuf.k[j].z * S[4 * j + 2];
        a3 += sbuf.k[j].w * S[4 * j + 3];
    }
    float kv = (a0 + a1) + (a2 + a3);
    kv += __shfl_xor_sync(0xffffffffu, kv, 8);
    kv += __shfl_xor_sync(0xffffffffu, kv, 16);

    const float eg = __expf(sbuf.g);
    const float delta = (sbuf.v - eg * kv) * sbuf.b;

    float o0 = 0.f, o1 = 0.f, o2 = 0.f, o3 = 0.f;
#pragma unroll
    for (int j = 0; j < 8; j++) {
        S[4 * j]     = eg * S[4 * j]     + sbuf.k[j].x * delta;
        o0 += sbuf.q[j].x * S[4 * j];
        S[4 * j + 1] = eg * S[4 * j + 1] + sbuf.k[j].y * delta;
        o1 += sbuf.q[j].y * S[4 * j + 1];
        S[4 * j + 2] = eg * S[4 * j + 2] + sbuf.k[j].z * delta;
        o2 += sbuf.q[j].z * S[4 * j + 2];
        S[4 * j + 3] = eg * S[4 * j + 3] + sbuf.k[j].w * delta;
        o3 += sbuf.q[j].w * S[4 * j + 3];
    }
    float o = (o0 + o1) + (o2 + o3);
    o += __shfl_xor_sync(0xffffffffu, o, 8);
    o += __shfl_xor_sync(0xffffffffu, o, 16);
    if (write_lane) *outp = o;
}

__global__ __launch_bounds__(128) void scan_kernel(
    const float* __restrict__ q, const float* __restrict__ k,
    const float* __restrict__ v, const float* __restrict__ g,
    const float* __restrict__ beta, float* __restrict__ core)
{
    const int wglob = blockIdx.x * 4 + (threadIdx.x >> 5);  // 0..511
    const int hv = wglob >> 4;
    const int octet = wglob & 15;
    const int hk = hv >> 1;
    const int lane = threadIdx.x & 31;
    const int dkq = lane >> 3;
    const int dvi = lane & 7;
    const int dv = octet * 8 + dvi;

    float S[32];
#pragma unroll
    for (int i = 0; i < 32; i++) S[i] = 0.f;

    const float* kp = k + (size_t)hk * DKC + dkq * 32;
    const float* qp = q + (size_t)hk * DKC + dkq * 32;
    const float* vp = v + (size_t)hv * DVC + dv;
    const float* gp = g + hv;
    const float* bp = beta + hv;
    float* op = core + (size_t)hv * DVC + dv;
    const int wl = (dkq == 0);

    ScanBuf A, B;
    scan_load(A, kp, qp, vp, gp, bp, 0);

    for (int t = 0; t < LSEQ; t += 2) {
        scan_load(B, kp, qp, vp, gp, bp, t + 1);
        scan_step(A, S, op + (size_t)t * VAL_DIM, wl);
        if (t + 2 < LSEQ) scan_load(A, kp, qp, vp, gp, bp, t + 2);
        scan_step(B, S, op + (size_t)(t + 1) * VAL_DIM, wl);
    }
}

// ---------------- RMS-ish norm + silu(z) gate -> hi/lo bf16 -------------------
__global__ __launch_bounds__(128) void normgate_kernel(
    const float* __restrict__ core, const float* __restrict__ proj,
    const float* __restrict__ norm_w,
    __nv_bfloat16* __restrict__ ghi, __nv_bfloat16* __restrict__ glo)
{
    const int bx = blockIdx.x;          // l * 32 + hv
    const int l = bx >> 5;
    const int hv = bx & 31;
    const int d = threadIdx.x;

    float c = core[(size_t)bx * 128 + d];
    float ss = c * c;
#pragma unroll
    for (int o = 16; o > 0; o >>= 1)
        ss += __shfl_xor_sync(0xffffffffu, ss, o);
    __shared__ float r4[4];
    if ((d & 31) == 0) r4[d >> 5] = ss;
    __syncthreads();
    float var = (r4[0] + r4[1] + r4[2] + r4[3]) * (1.f / 128.f);

    int hk = hv >> 1, gg = hv & 1;
    float z = proj[(size_t)l * NPROJ + hk * 768 + 512 + gg * 128 + d];
    float sz = z / (1.f + __expf(-z));
    float val = c * rsqrtf(var + 1e-6f) * norm_w[d] * sz;

    __nv_bfloat16 h = __float2bfloat16(val);
    size_t idx = (size_t)bx * 128 + d;
    ghi[idx] = h;
    glo[idx] = __float2bfloat16(val - __bfloat162float(h));
}

// ---------------- launch ------------------------------------------------------
extern "C" void kernel_launch(void* const* d_in, const int* in_sizes, int n_in,
                              void* d_out, int out_size)
{
    const float* hidden     = (const float*)d_in[0];
    const float* in_proj_w  = (const float*)d_in[1];
    const float* conv_w     = (const float*)d_in[2];
    const float* A_log      = (const float*)d_in[3];
    const float* dt_bias    = (const float*)d_in[4];
    const float* norm_w     = (const float*)d_in[5];
    const float* out_proj_w = (const float*)d_in[6];
    float* out = (float*)d_out;

    float *p_proj, *p_q, *p_k, *p_v, *p_g, *p_b, *p_core;
    __nv_bfloat16 *p_hh, *p_hl, *p_w1h, *p_w1l, *p_gh, *p_gl, *p_w2h, *p_w2l;
    cudaGetSymbolAddress((void**)&p_proj, g_proj);
    cudaGetSymbolAddress((void**)&p_q,    g_q);
    cudaGetSymbolAddress((void**)&p_k,    g_k);
    cudaGetSymbolAddress((void**)&p_v,    g_v);
    cudaGetSymbolAddress((void**)&p_g,    g_gdec);
    cudaGetSymbolAddress((void**)&p_b,    g_beta);
    cudaGetSymbolAddress((void**)&p_core, g_core);
    cudaGetSymbolAddress((void**)&p_hh,   g_hid_hi);
    cudaGetSymbolAddress((void**)&p_hl,   g_hid_lo);
    cudaGetSymbolAddress((void**)&p_w1h,  g_w1_hi);
    cudaGetSymbolAddress((void**)&p_w1l,  g_w1_lo);
    cudaGetSymbolAddress((void**)&p_gh,   g_gat_hi);
    cudaGetSymbolAddress((void**)&p_gl,   g_gat_lo);
    cudaGetSymbolAddress((void**)&p_w2h,  g_w2_hi);
    cudaGetSymbolAddress((void**)&p_w2l,  g_w2_lo);

    cudaFuncSetAttribute(gemm_b3_kernel,
                         cudaFuncAttributeMaxDynamicSharedMemorySize, GEMM_SMEM);

    // operand conversions
    {
        size_t n = (size_t)LSEQ * HDIM;
        conv_hl_kernel<<<(unsigned)((n + 255) / 256), 256>>>(hidden, p_hh, p_hl, n);
    }
    convT_kernel<<<dim3(NPAD1 / 32, HDIM / 32), 256>>>(in_proj_w, p_w1h, p_w1l,
                                                       HDIM, NPROJ);
    convT_kernel<<<dim3(HDIM / 32, VAL_DIM / 32), 256>>>(out_proj_w, p_w2h, p_w2l,
                                                         VAL_DIM, HDIM);

    // 1) proj = hidden @ in_proj_w   (4096 x 12352, K=2048)
    gemm_b3_kernel<<<dim3(NPAD1 / 128, LSEQ / 128), 256, GEMM_SMEM>>>(
        p_hh, p_hl, p_w1h, p_w1l, p_proj, LSEQ, NPROJ, HDIM);

    // 2) conv + silu + l2norm + gate params
    prep_kernel<<<LSEQ, 256>>>(p_proj, conv_w, A_log, dt_bias,
                               p_q, p_k, p_v, p_g, p_b);

    // 3) warp-autonomous sequential scan (512 warps)
    scan_kernel<<<128, 128>>>(p_q, p_k, p_v, p_g, p_b, p_core);

    // 4) norm + gate -> bf16 hi/lo
    normgate_kernel<<<LSEQ * NHV, 128>>>(p_core, p_proj, norm_w, p_gh, p_gl);

    // 5) out = gated @ out_proj_w   (4096 x 2048, K=4096)
    gemm_b3_kernel<<<dim3(HDIM / 128, LSEQ / 128), 256, GEMM_SMEM>>>(
        p_gh, p_gl, p_w2h, p_w2l, out, LSEQ, HDIM, VAL_DIM);
}

// round 8
// speedup vs baseline: 2.4313x; 1.2734x over previous
#include <cuda_runtime.h>
#include <cuda_bf16.h>
#include <cstdint>

// ---------------- problem constants ----------------
#define LSEQ   4096
#define HDIM   2048
#define NPROJ  12352      // QKVZ + BA
#define QKVZ_N 12288
#define KEY_DIM 2048
#define VAL_DIM 4096
#define NHV    32
#define DKC    128
#define DVC    128
#define NPAD1  12416      // 97*128, padded N for GEMM1 B rows

// ---------------- scratch (device globals; no cudaMalloc allowed) -------------
__device__ float g_proj [(size_t)LSEQ * NPROJ];
__device__ float g_q    [(size_t)LSEQ * KEY_DIM];
__device__ float g_k    [(size_t)LSEQ * KEY_DIM];
__device__ float g_v    [(size_t)LSEQ * VAL_DIM];
__device__ float g_gdec [(size_t)LSEQ * NHV];
__device__ float g_beta [(size_t)LSEQ * NHV];
__device__ float g_core [(size_t)LSEQ * VAL_DIM];

__device__ __nv_bfloat16 g_hid_hi[(size_t)LSEQ * HDIM];
__device__ __nv_bfloat16 g_hid_lo[(size_t)LSEQ * HDIM];
__device__ __nv_bfloat16 g_w1_hi [(size_t)NPAD1 * HDIM];   // in_proj_w^T [N,K]
__device__ __nv_bfloat16 g_w1_lo [(size_t)NPAD1 * HDIM];
__device__ __nv_bfloat16 g_gat_hi[(size_t)LSEQ * VAL_DIM];
__device__ __nv_bfloat16 g_gat_lo[(size_t)LSEQ * VAL_DIM];
__device__ __nv_bfloat16 g_w2_hi [(size_t)HDIM * VAL_DIM]; // out_proj_w^T [N,K]
__device__ __nv_bfloat16 g_w2_lo [(size_t)HDIM * VAL_DIM];

// ---------------- helpers -------------------------------------------------------
__device__ __forceinline__ uint32_t smem_u32(const void* p) {
    uint32_t a;
    asm("{ .reg .u64 t; cvta.to.shared.u64 t, %1; cvt.u32.u64 %0, t; }"
        : "=r"(a) : "l"(p));
    return a;
}

// 64B-row swizzle: conflict-free for 16B-granular ldmatrix/cp.async on 64B rows
#define SW64(x) ((x) ^ (((x) >> 3) & 0x30))

__device__ __forceinline__ void cpa16(uint32_t s, const void* g) {
    asm volatile("cp.async.cg.shared.global [%0], [%1], 16;" :: "r"(s), "l"(g));
}
__device__ __forceinline__ void cpa4(uint32_t s, const void* g) {
    asm volatile("cp.async.ca.shared.global [%0], [%1], 4;" :: "r"(s), "l"(g));
}
__device__ __forceinline__ void cpa_commit() {
    asm volatile("cp.async.commit_group;" ::: "memory");
}
__device__ __forceinline__ void cpa_wait1() {
    asm volatile("cp.async.wait_group 1;" ::: "memory");
}
__device__ __forceinline__ void cpa_wait0() {
    asm volatile("cp.async.wait_group 0;" ::: "memory");
}
__device__ __forceinline__ void cpa_wait7() {
    asm volatile("cp.async.wait_group 7;" ::: "memory");
}

__device__ __forceinline__ void ldsm4(uint32_t& r0, uint32_t& r1, uint32_t& r2,
                                      uint32_t& r3, uint32_t a) {
    asm volatile("ldmatrix.sync.aligned.m8n8.x4.shared.b16 {%0,%1,%2,%3}, [%4];"
                 : "=r"(r0), "=r"(r1), "=r"(r2), "=r"(r3) : "r"(a));
}

__device__ __forceinline__ void mma16816(float* c, const uint32_t* a,
                                         const uint32_t* b) {
    asm volatile(
        "mma.sync.aligned.m16n8k16.row.col.f32.bf16.bf16.f32 "
        "{%0,%1,%2,%3}, {%4,%5,%6,%7}, {%8,%9}, {%0,%1,%2,%3};"
        : "+f"(c[0]), "+f"(c[1]), "+f"(c[2]), "+f"(c[3])
        : "r"(a[0]), "r"(a[1]), "r"(a[2]), "r"(a[3]), "r"(b[0]), "r"(b[1]));
}

// ---------------- bf16x3 mma.sync GEMM (unchanged from R6) ---------------------
#define GSTAGE 32768
#define NSTAGE 3
#define GEMM_SMEM (NSTAGE * GSTAGE)

__global__ __launch_bounds__(256, 2) void gemm_b3_kernel(
    const __nv_bfloat16* __restrict__ Ahi, const __nv_bfloat16* __restrict__ Alo,
    const __nv_bfloat16* __restrict__ Bhi, const __nv_bfloat16* __restrict__ Blo,
    float* __restrict__ C, int M, int N, int K)
{
    extern __shared__ char smem[];
    const uint32_t sb = smem_u32(smem);
    const int tid = threadIdx.x;
    const int wid = tid >> 5;
    const int lane = tid & 31;
    const int wm = wid >> 1;       // 0..3
    const int wn = wid & 1;        // 0..1
    const int bm = blockIdx.y * 128;
    const int bn = blockIdx.x * 128;

    const int rowh = tid >> 2;     // 0..63
    const int kc = tid & 3;        // 16B chunk within 64B row
    const __nv_bfloat16* gp[4];
    gp[0] = Ahi + (size_t)bm * K;
    gp[1] = Alo + (size_t)bm * K;
    gp[2] = Bhi + (size_t)bn * K;
    gp[3] = Blo + (size_t)bn * K;

    float acc[2][8][4];
#pragma unroll
    for (int i = 0; i < 2; i++)
#pragma unroll
        for (int j = 0; j < 8; j++)
#pragma unroll
            for (int x = 0; x < 4; x++) acc[i][j][x] = 0.f;

    const int nk = K >> 5;

    uint32_t aoff[2][2], boff[4][2];   // [tile][ks]
#pragma unroll
    for (int t = 0; t < 2; t++)
#pragma unroll
        for (int ks = 0; ks < 2; ks++)
            aoff[t][ks] = SW64(((wm * 32 + t * 16 + (lane & 15)) << 6)
                               + ks * 32 + ((lane >> 4) << 4));
#pragma unroll
    for (int p = 0; p < 4; p++)
#pragma unroll
        for (int ks = 0; ks < 2; ks++)
            boff[p][ks] = SW64(((wn * 64 + p * 16 + ((lane >> 4) << 3) + (lane & 7)) << 6)
                               + ks * 32 + (((lane >> 3) & 1) << 4))
                          + 16384;

#pragma unroll
    for (int s = 0; s < 2; s++) {
        const size_t k0 = (size_t)s << 5;
        const uint32_t stb = sb + s * GSTAGE;
#pragma unroll
        for (int j = 0; j < 8; j++) {
            const int tile = j >> 1;
            const int row = ((j & 1) << 6) + rowh;
            cpa16(stb + (tile << 13) + SW64((row << 6) + kc * 16),
                  gp[tile] + (size_t)row * K + k0 + kc * 8);
        }
        cpa_commit();
    }

    int sc = 0;
    int sp = 2;
    for (int kt = 0; kt < nk; ++kt) {
        if (kt < nk - 1) cpa_wait1();
        else             cpa_wait0();
        __syncthreads();

        if (kt + 2 < nk) {
            const size_t k0 = (size_t)(kt + 2) << 5;
            const uint32_t stb = sb + sp * GSTAGE;
#pragma unroll
            for (int j = 0; j < 8; j++) {
                const int tile = j >> 1;
                const int row = ((j & 1) << 6) + rowh;
                cpa16(stb + (tile << 13) + SW64((row << 6) + kc * 16),
                      gp[tile] + (size_t)row * K + k0 + kc * 8);
            }
            cpa_commit();
        }

        const uint32_t base = sb + sc * GSTAGE;
        if (++sc == NSTAGE) sc = 0;
        if (++sp == NSTAGE) sp = 0;

#pragma unroll
        for (int ks = 0; ks < 2; ks++) {
            uint32_t ah[2][4], al[2][4], bh[8][2];
#pragma unroll
            for (int t = 0; t < 2; t++) {
                ldsm4(ah[t][0], ah[t][1], ah[t][2], ah[t][3], base + aoff[t][ks]);
                ldsm4(al[t][0], al[t][1], al[t][2], al[t][3], base + 8192 + aoff[t][ks]);
            }
#pragma unroll
            for (int p = 0; p < 4; p++)
                ldsm4(bh[2 * p][0], bh[2 * p][1], bh[2 * p + 1][0], bh[2 * p + 1][1],
                      base + boff[p][ks]);
#pragma unroll
            for (int i = 0; i < 2; i++)
#pragma unroll
                for (int j = 0; j < 8; j++)
                    mma16816(acc[i][j], ah[i], bh[j]);
#pragma unroll
            for (int i = 0; i < 2; i++)
#pragma unroll
                for (int j = 0; j < 8; j++)
                    mma16816(acc[i][j], al[i], bh[j]);
#pragma unroll
            for (int p = 0; p < 4; p++) {
                uint32_t bl0[2], bl1[2];
                ldsm4(bl0[0], bl0[1], bl1[0], bl1[1],
                      base + 8192 + boff[p][ks]);
                mma16816(acc[0][2 * p],     ah[0], bl0);
                mma16816(acc[1][2 * p],     ah[1], bl0);
                mma16816(acc[0][2 * p + 1], ah[0], bl1);
                mma16816(acc[1][2 * p + 1], ah[1], bl1);
            }
        }
    }

#pragma unroll
    for (int i = 0; i < 2; i++) {
        const int r0 = bm + wm * 32 + i * 16 + (lane >> 2);
#pragma unroll
        for (int j = 0; j < 8; j++) {
            const int col = bn + wn * 64 + j * 8 + (lane & 3) * 2;
            if (col < N) {
                *(float2*)&C[(size_t)r0 * N + col] =
                    make_float2(acc[i][j][0], acc[i][j][1]);
                *(float2*)&C[(size_t)(r0 + 8) * N + col] =
                    make_float2(acc[i][j][2], acc[i][j][3]);
            }
        }
    }
}

// ---------------- conversions --------------------------------------------------
__global__ __launch_bounds__(256) void conv_hl_kernel(
    const float* __restrict__ X, __nv_bfloat16* __restrict__ hi,
    __nv_bfloat16* __restrict__ lo, size_t n)
{
    size_t i = (size_t)blockIdx.x * 256 + threadIdx.x;
    if (i < n) {
        float x = X[i];
        __nv_bfloat16 h = __float2bfloat16(x);
        hi[i] = h;
        lo[i] = __float2bfloat16(x - __bfloat162float(h));
    }
}

// W[K, N] fp32 -> hi/lo bf16 [Npad, K] (transpose); rows n >= N are zero.
__global__ __launch_bounds__(256) void convT_kernel(
    const float* __restrict__ W, __nv_bfloat16* __restrict__ hi,
    __nv_bfloat16* __restrict__ lo, int K, int N)
{
    __shared__ float t[32][33];
    const int nb = blockIdx.x * 32;
    const int kb = blockIdx.y * 32;
    const int tx = threadIdx.x & 31;
    const int ty = threadIdx.x >> 5;
#pragma unroll
    for (int p = 0; p < 4; p++) {
        int r = ty + p * 8;                 // k row
        int n = nb + tx;
        t[r][tx] = (n < N) ? W[(size_t)(kb + r) * N + n] : 0.f;
    }
    __syncthreads();
#pragma unroll
    for (int p = 0; p < 4; p++) {
        int r = ty + p * 8;                 // output n row
        float x = t[tx][r];
        __nv_bfloat16 h = __float2bfloat16(x);
        __nv_bfloat16 l = __float2bfloat16(x - __bfloat162float(h));
        size_t o = (size_t)(nb + r) * K + kb + tx;
        hi[o] = h;
        lo[o] = l;
    }
}

// ---------------- conv(K=4) + silu + l2norm + gating prep ---------------------
__global__ __launch_bounds__(256) void prep_kernel(
    const float* __restrict__ proj, const float* __restrict__ conv_w,
    const float* __restrict__ A_log, const float* __restrict__ dt_bias,
    float* __restrict__ qo, float* __restrict__ ko, float* __restrict__ vo,
    float* __restrict__ go, float* __restrict__ bo)
{
    const int l = blockIdx.x;
    const int tid = threadIdx.x;
    __shared__ float buf[8192];
    __shared__ float inv[32];

    for (int f = tid; f < 8192; f += 256) {
        int col;
        if (f < 2048) {
            col = (f >> 7) * 768 + (f & 127);
        } else if (f < 4096) {
            int ff = f - 2048;
            col = (ff >> 7) * 768 + 128 + (ff & 127);
        } else {
            int ff = f - 4096;
            int hv = ff >> 7;
            col = (hv >> 1) * 768 + 256 + (hv & 1) * 128 + (ff & 127);
        }
        float4 w4 = *(const float4*)(conv_w + (size_t)f * 4);
        const float* pc = proj + col;
        float s;
        if (l >= 3) {
            s = w4.x * pc[(size_t)(l - 3) * NPROJ]
              + w4.y * pc[(size_t)(l - 2) * NPROJ]
              + w4.z * pc[(size_t)(l - 1) * NPROJ]
              + w4.w * pc[(size_t)l       * NPROJ];
        } else {
            s = w4.w * pc[(size_t)l * NPROJ];
            if (l >= 1) s += w4.z * pc[(size_t)(l - 1) * NPROJ];
            if (l >= 2) s += w4.y * pc[(size_t)(l - 2) * NPROJ];
        }
        s = s / (1.f + __expf(-s));
        buf[f] = s;
    }
    __syncthreads();

    {
        int grp = tid >> 3, sub = tid & 7;
        int base = (grp < 16) ? grp * 128 : 2048 + (grp - 16) * 128;
        float ss = 0.f;
#pragma unroll
        for (int i = 0; i < 16; i++) {
            float x = buf[base + sub * 16 + i];
            ss += x * x;
        }
        ss += __shfl_xor_sync(0xffffffffu, ss, 4);
        ss += __shfl_xor_sync(0xffffffffu, ss, 2);
        ss += __shfl_xor_sync(0xffffffffu, ss, 1);
        if (sub == 0) inv[grp] = rsqrtf(ss + 1e-6f);
    }
    __syncthreads();

    const float qscale = 0.08838834764831845f;  // 128^-0.5
    for (int f = tid; f < 2048; f += 256) {
        qo[(size_t)l * 2048 + f] = buf[f]        * inv[f >> 7] * qscale;
        ko[(size_t)l * 2048 + f] = buf[2048 + f] * inv[16 + (f >> 7)];
    }
    for (int f = tid; f < 4096; f += 256)
        vo[(size_t)l * 4096 + f] = buf[4096 + f];

    if (tid < 32) {
        const float* prow = proj + (size_t)l * NPROJ;
        int hv = tid, hk = hv >> 1, gg = hv & 1;
        float bb = prow[QKVZ_N + hk * 4 + gg];
        float aa = prow[QKVZ_N + hk * 4 + 2 + gg];
        bo[(size_t)l * 32 + hv] = 1.f / (1.f + __expf(-bb));
        float x = aa + dt_bias[hv];
        float sp = (x > 20.f) ? x : log1pf(__expf(x));
        go[(size_t)l * 32 + hv] = -__expf(A_log[hv]) * sp;
    }
}

// ---------------- warp-autonomous delta-rule scan + cp.async smem ring --------
// One warp per (hv, 8-column dv octet): 512 warps. lane = dkq*8 + dvi.
// Each warp owns a private 8-stage smem ring (k 512B + q 512B + v 32B + g,b).
// cp.async prefetches 8 steps ahead; wait_group 7 + __syncwarp retires oldest.
// k/q stored slice-interleaved: global float f -> smem (f/16)*64B + (f%16/4)*16B,
// so the 4 dk-slices sit 16B apart (conflict-free LDS.128 with 8-lane bcast).
// Lane's dk partition is permuted vs naive - harmless (butterfly sums all).
#define SNS 8
#define SSTRIDE_B 1088      // per-stage bytes: k 512 | q 512 | v 32 | g 4 | b 4 | pad

__global__ __launch_bounds__(128) void scan_kernel(
    const float* __restrict__ q, const float* __restrict__ k,
    const float* __restrict__ v, const float* __restrict__ g,
    const float* __restrict__ beta, float* __restrict__ core)
{
    __shared__ char ring[4][SNS][SSTRIDE_B];

    const int w = threadIdx.x >> 5;
    const int wglob = blockIdx.x * 4 + w;                 // 0..511
    const int hv = wglob >> 4;
    const int octet = wglob & 15;
    const int hk = hv >> 1;
    const int lane = threadIdx.x & 31;
    const int dkq = lane >> 3;     // slice index 0..3
    const int dvi = lane & 7;

    const float* kp = k + (size_t)hk * DKC;               // + t*KEY_DIM
    const float* qp = q + (size_t)hk * DKC;
    const float* vp = v + (size_t)hv * DVC + octet * 8;   // + t*VAL_DIM
    const float* gp = g + hv;                             // + t*NHV
    const float* bp = beta + hv;
    float* op = core + (size_t)hv * DVC + octet * 8 + dvi;
    const int wl = (dkq == 0);

    // per-lane cp.async targets within a stage
    const uint32_t rbase = smem_u32(&ring[w][0][0]);
    const uint32_t koff = (uint32_t)(((lane >> 2) << 6) | ((lane & 3) << 4));

    float S[32];
#pragma unroll
    for (int i = 0; i < 32; i++) S[i] = 0.f;

    // prologue: fill all 8 stages (t = 0..7)
#pragma unroll
    for (int s = 0; s < SNS; s++) {
        const uint32_t st = rbase + s * SSTRIDE_B;
        const size_t t = s;
        cpa16(st + koff,       kp + t * KEY_DIM + lane * 4);
        cpa16(st + 512 + koff, qp + t * KEY_DIM + lane * 4);
        if (lane < 8)       cpa4(st + 1024 + lane * 4, vp + t * VAL_DIM + lane);
        else if (lane == 8) cpa4(st + 1056, gp + t * NHV);
        else if (lane == 9) cpa4(st + 1060, bp + t * NHV);
        cpa_commit();
    }

    int slot = 0;
    for (int t = 0; t < LSEQ; t++) {
        cpa_wait7();            // oldest group (this slot) has landed
        __syncwarp();

        const char* sp_ = &ring[w][slot][0];
        // read k/q slices: 8 x float4 each, conflict-free (bcast x8, 4 lines/64B)
        float4 kf[8], qf[8];
#pragma unroll
        for (int j = 0; j < 8; j++) {
            kf[j] = *(const float4*)(sp_ + j * 64 + dkq * 16);
            qf[j] = *(const float4*)(sp_ + 512 + j * 64 + dkq * 16);
        }
        const float vt = *(const float*)(sp_ + 1024 + dvi * 4);
        const float gt = *(const float*)(sp_ + 1056);
        const float bt = *(const float*)(sp_ + 1060);
        __syncwarp();           // all lanes done reading before refill

        // refill this slot with step t+8 (clamped; redundant loads at tail)
        {
            const size_t tn = (t + SNS < LSEQ) ? (size_t)(t + SNS) : (size_t)(LSEQ - 1);
            const uint32_t st = rbase + slot * SSTRIDE_B;
            cpa16(st + koff,       kp + tn * KEY_DIM + lane * 4);
            cpa16(st + 512 + koff, qp + tn * KEY_DIM + lane * 4);
            if (lane < 8)       cpa4(st + 1024 + lane * 4, vp + tn * VAL_DIM + lane);
            else if (lane == 8) cpa4(st + 1056, gp + tn * NHV);
            else if (lane == 9) cpa4(st + 1060, bp + tn * NHV);
            cpa_commit();
        }
        if (++slot == SNS) slot = 0;

        // kv = k . S (local) -> butterfly over the 4 slices
        float a0 = 0.f, a1 = 0.f, a2 = 0.f, a3 = 0.f;
#pragma unroll
        for (int j = 0; j < 8; j++) {
            a0 += kf[j].x * S[4 * j];
            a1 += kf[j].y * S[4 * j + 1];
            a2 += kf[j].z * S[4 * j + 2];
            a3 += kf[j].w * S[4 * j + 3];
        }
        float kv = (a0 + a1) + (a2 + a3);
        kv += __shfl_xor_sync(0xffffffffu, kv, 8);
        kv += __shfl_xor_sync(0xffffffffu, kv, 16);

        const float eg = __expf(gt);
        const float delta = (vt - eg * kv) * bt;

        float o0 = 0.f, o1 = 0.f, o2 = 0.f, o3 = 0.f;
#pragma unroll
        for (int j = 0; j < 8; j++) {
            S[4 * j]     = eg * S[4 * j]     + kf[j].x * delta;
            o0 += qf[j].x * S[4 * j];
            S[4 * j + 1] = eg * S[4 * j + 1] + kf[j].y * delta;
            o1 += qf[j].y * S[4 * j + 1];
            S[4 * j + 2] = eg * S[4 * j + 2] + kf[j].z * delta;
            o2 += qf[j].z * S[4 * j + 2];
            S[4 * j + 3] = eg * S[4 * j + 3] + kf[j].w * delta;
            o3 += qf[j].w * S[4 * j + 3];
        }
        float o = (o0 + o1) + (o2 + o3);
        o += __shfl_xor_sync(0xffffffffu, o, 8);
        o += __shfl_xor_sync(0xffffffffu, o, 16);
        if (wl) op[(size_t)t * VAL_DIM] = o;
    }
}

// ---------------- RMS-ish norm + silu(z) gate -> hi/lo bf16 -------------------
__global__ __launch_bounds__(128) void normgate_kernel(
    const float* __restrict__ core, const float* __restrict__ proj,
    const float* __restrict__ norm_w,
    __nv_bfloat16* __restrict__ ghi, __nv_bfloat16* __restrict__ glo)
{
    const int bx = blockIdx.x;          // l * 32 + hv
    const int l = bx >> 5;
    const int hv = bx & 31;
    const int d = threadIdx.x;

    float c = core[(size_t)bx * 128 + d];
    float ss = c * c;
#pragma unroll
    for (int o = 16; o > 0; o >>= 1)
        ss += __shfl_xor_sync(0xffffffffu, ss, o);
    __shared__ float r4[4];
    if ((d & 31) == 0) r4[d >> 5] = ss;
    __syncthreads();
    float var = (r4[0] + r4[1] + r4[2] + r4[3]) * (1.f / 128.f);

    int hk = hv >> 1, gg = hv & 1;
    float z = proj[(size_t)l * NPROJ + hk * 768 + 512 + gg * 128 + d];
    float sz = z / (1.f + __expf(-z));
    float val = c * rsqrtf(var + 1e-6f) * norm_w[d] * sz;

    __nv_bfloat16 h = __float2bfloat16(val);
    size_t idx = (size_t)bx * 128 + d;
    ghi[idx] = h;
    glo[idx] = __float2bfloat16(val - __bfloat162float(h));
}

// ---------------- launch ------------------------------------------------------
extern "C" void kernel_launch(void* const* d_in, const int* in_sizes, int n_in,
                              void* d_out, int out_size)
{
    const float* hidden     = (const float*)d_in[0];
    const float* in_proj_w  = (const float*)d_in[1];
    const float* conv_w     = (const float*)d_in[2];
    const float* A_log      = (const float*)d_in[3];
    const float* dt_bias    = (const float*)d_in[4];
    const float* norm_w     = (const float*)d_in[5];
    const float* out_proj_w = (const float*)d_in[6];
    float* out = (float*)d_out;

    float *p_proj, *p_q, *p_k, *p_v, *p_g, *p_b, *p_core;
    __nv_bfloat16 *p_hh, *p_hl, *p_w1h, *p_w1l, *p_gh, *p_gl, *p_w2h, *p_w2l;
    cudaGetSymbolAddress((void**)&p_proj, g_proj);
    cudaGetSymbolAddress((void**)&p_q,    g_q);
    cudaGetSymbolAddress((void**)&p_k,    g_k);
    cudaGetSymbolAddress((void**)&p_v,    g_v);
    cudaGetSymbolAddress((void**)&p_g,    g_gdec);
    cudaGetSymbolAddress((void**)&p_b,    g_beta);
    cudaGetSymbolAddress((void**)&p_core, g_core);
    cudaGetSymbolAddress((void**)&p_hh,   g_hid_hi);
    cudaGetSymbolAddress((void**)&p_hl,   g_hid_lo);
    cudaGetSymbolAddress((void**)&p_w1h,  g_w1_hi);
    cudaGetSymbolAddress((void**)&p_w1l,  g_w1_lo);
    cudaGetSymbolAddress((void**)&p_gh,   g_gat_hi);
    cudaGetSymbolAddress((void**)&p_gl,   g_gat_lo);
    cudaGetSymbolAddress((void**)&p_w2h,  g_w2_hi);
    cudaGetSymbolAddress((void**)&p_w2l,  g_w2_lo);

    cudaFuncSetAttribute(gemm_b3_kernel,
                         cudaFuncAttributeMaxDynamicSharedMemorySize, GEMM_SMEM);

    // operand conversions
    {
        size_t n = (size_t)LSEQ * HDIM;
        conv_hl_kernel<<<(unsigned)((n + 255) / 256), 256>>>(hidden, p_hh, p_hl, n);
    }
    convT_kernel<<<dim3(NPAD1 / 32, HDIM / 32), 256>>>(in_proj_w, p_w1h, p_w1l,
                                                       HDIM, NPROJ);
    convT_kernel<<<dim3(HDIM / 32, VAL_DIM / 32), 256>>>(out_proj_w, p_w2h, p_w2l,
                                                         VAL_DIM, HDIM);

    // 1) proj = hidden @ in_proj_w   (4096 x 12352, K=2048)
    gemm_b3_kernel<<<dim3(NPAD1 / 128, LSEQ / 128), 256, GEMM_SMEM>>>(
        p_hh, p_hl, p_w1h, p_w1l, p_proj, LSEQ, NPROJ, HDIM);

    // 2) conv + silu + l2norm + gate params
    prep_kernel<<<LSEQ, 256>>>(p_proj, conv_w, A_log, dt_bias,
                               p_q, p_k, p_v, p_g, p_b);

    // 3) warp-autonomous sequential scan (512 warps, smem ring prefetch)
    scan_kernel<<<128, 128>>>(p_q, p_k, p_v, p_g, p_b, p_core);

    // 4) norm + gate -> bf16 hi/lo
    normgate_kernel<<<LSEQ * NHV, 128>>>(p_core, p_proj, norm_w, p_gh, p_gl);

    // 5) out = gated @ out_proj_w   (4096 x 2048, K=4096)
    gemm_b3_kernel<<<dim3(HDIM / 128, LSEQ / 128), 256, GEMM_SMEM>>>(
        p_gh, p_gl, p_w2h, p_w2l, out, LSEQ, HDIM, VAL_DIM);
}

// round 9
// speedup vs baseline: 2.5046x; 1.0302x over previous
#include <cuda_runtime.h>
#include <cuda_bf16.h>
#include <cstdint>

// ---------------- problem constants ----------------
#define LSEQ   4096
#define HDIM   2048
#define NPROJ  12352      // QKVZ + BA
#define QKVZ_N 12288
#define KEY_DIM 2048
#define VAL_DIM 4096
#define NHV    32
#define DKC    128
#define DVC    128
#define NPAD1  12416      // 97*128, padded N for GEMM1 B rows

// ---------------- scratch (device globals; no cudaMalloc allowed) -------------
__device__ float g_proj [(size_t)LSEQ * NPROJ];
__device__ float g_q    [(size_t)LSEQ * KEY_DIM];
__device__ float g_k    [(size_t)LSEQ * KEY_DIM];
__device__ float g_v    [(size_t)LSEQ * VAL_DIM];
__device__ float g_gdec [(size_t)LSEQ * NHV];   // holds exp(g) now
__device__ float g_beta [(size_t)LSEQ * NHV];
__device__ float g_core [(size_t)LSEQ * VAL_DIM];

__device__ __nv_bfloat16 g_hid_hi[(size_t)LSEQ * HDIM];
__device__ __nv_bfloat16 g_hid_lo[(size_t)LSEQ * HDIM];
__device__ __nv_bfloat16 g_w1_hi [(size_t)NPAD1 * HDIM];   // in_proj_w^T [N,K]
__device__ __nv_bfloat16 g_w1_lo [(size_t)NPAD1 * HDIM];
__device__ __nv_bfloat16 g_gat_hi[(size_t)LSEQ * VAL_DIM];
__device__ __nv_bfloat16 g_gat_lo[(size_t)LSEQ * VAL_DIM];
__device__ __nv_bfloat16 g_w2_hi [(size_t)HDIM * VAL_DIM]; // out_proj_w^T [N,K]
__device__ __nv_bfloat16 g_w2_lo [(size_t)HDIM * VAL_DIM];

// ---------------- helpers -------------------------------------------------------
__device__ __forceinline__ uint32_t smem_u32(const void* p) {
    uint32_t a;
    asm("{ .reg .u64 t; cvta.to.shared.u64 t, %1; cvt.u32.u64 %0, t; }"
        : "=r"(a) : "l"(p));
    return a;
}

// 64B-row swizzle: conflict-free for 16B-granular ldmatrix/cp.async on 64B rows
#define SW64(x) ((x) ^ (((x) >> 3) & 0x30))

__device__ __forceinline__ void cpa16(uint32_t s, const void* g) {
    asm volatile("cp.async.cg.shared.global [%0], [%1], 16;" :: "r"(s), "l"(g));
}
__device__ __forceinline__ void cpa4p(uint32_t s, const void* g, uint32_t p) {
    asm volatile("{ .reg .pred q; setp.ne.u32 q, %2, 0;"
                 " @q cp.async.ca.shared.global [%0], [%1], 4; }"
                 :: "r"(s), "l"(g), "r"(p));
}
__device__ __forceinline__ void cpa_commit() {
    asm volatile("cp.async.commit_group;" ::: "memory");
}
__device__ __forceinline__ void cpa_wait1() {
    asm volatile("cp.async.wait_group 1;" ::: "memory");
}
__device__ __forceinline__ void cpa_wait0() {
    asm volatile("cp.async.wait_group 0;" ::: "memory");
}
__device__ __forceinline__ void cpa_wait7() {
    asm volatile("cp.async.wait_group 7;" ::: "memory");
}

__device__ __forceinline__ void ldsm4(uint32_t& r0, uint32_t& r1, uint32_t& r2,
                                      uint32_t& r3, uint32_t a) {
    asm volatile("ldmatrix.sync.aligned.m8n8.x4.shared.b16 {%0,%1,%2,%3}, [%4];"
                 : "=r"(r0), "=r"(r1), "=r"(r2), "=r"(r3) : "r"(a));
}

__device__ __forceinline__ void mma16816(float* c, const uint32_t* a,
                                         const uint32_t* b) {
    asm volatile(
        "mma.sync.aligned.m16n8k16.row.col.f32.bf16.bf16.f32 "
        "{%0,%1,%2,%3}, {%4,%5,%6,%7}, {%8,%9}, {%0,%1,%2,%3};"
        : "+f"(c[0]), "+f"(c[1]), "+f"(c[2]), "+f"(c[3])
        : "r"(a[0]), "r"(a[1]), "r"(a[2]), "r"(a[3]), "r"(b[0]), "r"(b[1]));
}

// ---------------- bf16x3 mma.sync GEMM (unchanged from R6) ---------------------
#define GSTAGE 32768
#define NSTAGE 3
#define GEMM_SMEM (NSTAGE * GSTAGE)

__global__ __launch_bounds__(256, 2) void gemm_b3_kernel(
    const __nv_bfloat16* __restrict__ Ahi, const __nv_bfloat16* __restrict__ Alo,
    const __nv_bfloat16* __restrict__ Bhi, const __nv_bfloat16* __restrict__ Blo,
    float* __restrict__ C, int M, int N, int K)
{
    extern __shared__ char smem[];
    const uint32_t sb = smem_u32(smem);
    const int tid = threadIdx.x;
    const int wid = tid >> 5;
    const int lane = tid & 31;
    const int wm = wid >> 1;       // 0..3
    const int wn = wid & 1;        // 0..1
    const int bm = blockIdx.y * 128;
    const int bn = blockIdx.x * 128;

    const int rowh = tid >> 2;     // 0..63
    const int kc = tid & 3;        // 16B chunk within 64B row
    const __nv_bfloat16* gp[4];
    gp[0] = Ahi + (size_t)bm * K;
    gp[1] = Alo + (size_t)bm * K;
    gp[2] = Bhi + (size_t)bn * K;
    gp[3] = Blo + (size_t)bn * K;

    float acc[2][8][4];
#pragma unroll
    for (int i = 0; i < 2; i++)
#pragma unroll
        for (int j = 0; j < 8; j++)
#pragma unroll
            for (int x = 0; x < 4; x++) acc[i][j][x] = 0.f;

    const int nk = K >> 5;

    uint32_t aoff[2][2], boff[4][2];   // [tile][ks]
#pragma unroll
    for (int t = 0; t < 2; t++)
#pragma unroll
        for (int ks = 0; ks < 2; ks++)
            aoff[t][ks] = SW64(((wm * 32 + t * 16 + (lane & 15)) << 6)
                               + ks * 32 + ((lane >> 4) << 4));
#pragma unroll
    for (int p = 0; p < 4; p++)
#pragma unroll
        for (int ks = 0; ks < 2; ks++)
            boff[p][ks] = SW64(((wn * 64 + p * 16 + ((lane >> 4) << 3) + (lane & 7)) << 6)
                               + ks * 32 + (((lane >> 3) & 1) << 4))
                          + 16384;

#pragma unroll
    for (int s = 0; s < 2; s++) {
        const size_t k0 = (size_t)s << 5;
        const uint32_t stb = sb + s * GSTAGE;
#pragma unroll
        for (int j = 0; j < 8; j++) {
            const int tile = j >> 1;
            const int row = ((j & 1) << 6) + rowh;
            cpa16(stb + (tile << 13) + SW64((row << 6) + kc * 16),
                  gp[tile] + (size_t)row * K + k0 + kc * 8);
        }
        cpa_commit();
    }

    int sc = 0;
    int sp = 2;
    for (int kt = 0; kt < nk; ++kt) {
        if (kt < nk - 1) cpa_wait1();
        else             cpa_wait0();
        __syncthreads();

        if (kt + 2 < nk) {
            const size_t k0 = (size_t)(kt + 2) << 5;
            const uint32_t stb = sb + sp * GSTAGE;
#pragma unroll
            for (int j = 0; j < 8; j++) {
                const int tile = j >> 1;
                const int row = ((j & 1) << 6) + rowh;
                cpa16(stb + (tile << 13) + SW64((row << 6) + kc * 16),
                      gp[tile] + (size_t)row * K + k0 + kc * 8);
            }
            cpa_commit();
        }

        const uint32_t base = sb + sc * GSTAGE;
        if (++sc == NSTAGE) sc = 0;
        if (++sp == NSTAGE) sp = 0;

#pragma unroll
        for (int ks = 0; ks < 2; ks++) {
            uint32_t ah[2][4], al[2][4], bh[8][2];
#pragma unroll
            for (int t = 0; t < 2; t++) {
                ldsm4(ah[t][0], ah[t][1], ah[t][2], ah[t][3], base + aoff[t][ks]);
                ldsm4(al[t][0], al[t][1], al[t][2], al[t][3], base + 8192 + aoff[t][ks]);
            }
#pragma unroll
            for (int p = 0; p < 4; p++)
                ldsm4(bh[2 * p][0], bh[2 * p][1], bh[2 * p + 1][0], bh[2 * p + 1][1],
                      base + boff[p][ks]);
#pragma unroll
            for (int i = 0; i < 2; i++)
#pragma unroll
                for (int j = 0; j < 8; j++)
                    mma16816(acc[i][j], ah[i], bh[j]);
#pragma unroll
            for (int i = 0; i < 2; i++)
#pragma unroll
                for (int j = 0; j < 8; j++)
                    mma16816(acc[i][j], al[i], bh[j]);
#pragma unroll
            for (int p = 0; p < 4; p++) {
                uint32_t bl0[2], bl1[2];
                ldsm4(bl0[0], bl0[1], bl1[0], bl1[1],
                      base + 8192 + boff[p][ks]);
                mma16816(acc[0][2 * p],     ah[0], bl0);
                mma16816(acc[1][2 * p],     ah[1], bl0);
                mma16816(acc[0][2 * p + 1], ah[0], bl1);
                mma16816(acc[1][2 * p + 1], ah[1], bl1);
            }
        }
    }

#pragma unroll
    for (int i = 0; i < 2; i++) {
        const int r0 = bm + wm * 32 + i * 16 + (lane >> 2);
#pragma unroll
        for (int j = 0; j < 8; j++) {
            const int col = bn + wn * 64 + j * 8 + (lane & 3) * 2;
            if (col < N) {
                *(float2*)&C[(size_t)r0 * N + col] =
                    make_float2(acc[i][j][0], acc[i][j][1]);
                *(float2*)&C[(size_t)(r0 + 8) * N + col] =
                    make_float2(acc[i][j][2], acc[i][j][3]);
            }
        }
    }
}

// ---------------- conversions --------------------------------------------------
__global__ __launch_bounds__(256) void conv_hl_kernel(
    const float* __restrict__ X, __nv_bfloat16* __restrict__ hi,
    __nv_bfloat16* __restrict__ lo, size_t n)
{
    size_t i = (size_t)blockIdx.x * 256 + threadIdx.x;
    if (i < n) {
        float x = X[i];
        __nv_bfloat16 h = __float2bfloat16(x);
        hi[i] = h;
        lo[i] = __float2bfloat16(x - __bfloat162float(h));
    }
}

// W[K, N] fp32 -> hi/lo bf16 [Npad, K] (transpose); rows n >= N are zero.
__global__ __launch_bounds__(256) void convT_kernel(
    const float* __restrict__ W, __nv_bfloat16* __restrict__ hi,
    __nv_bfloat16* __restrict__ lo, int K, int N)
{
    __shared__ float t[32][33];
    const int nb = blockIdx.x * 32;
    const int kb = blockIdx.y * 32;
    const int tx = threadIdx.x & 31;
    const int ty = threadIdx.x >> 5;
#pragma unroll
    for (int p = 0; p < 4; p++) {
        int r = ty + p * 8;                 // k row
        int n = nb + tx;
        t[r][tx] = (n < N) ? W[(size_t)(kb + r) * N + n] : 0.f;
    }
    __syncthreads();
#pragma unroll
    for (int p = 0; p < 4; p++) {
        int r = ty + p * 8;                 // output n row
        float x = t[tx][r];
        __nv_bfloat16 h = __float2bfloat16(x);
        __nv_bfloat16 l = __float2bfloat16(x - __bfloat162float(h));
        size_t o = (size_t)(nb + r) * K + kb + tx;
        hi[o] = h;
        lo[o] = l;
    }
}

// ---------------- conv(K=4) + silu + l2norm + gating prep ---------------------
__global__ __launch_bounds__(256) void prep_kernel(
    const float* __restrict__ proj, const float* __restrict__ conv_w,
    const float* __restrict__ A_log, const float* __restrict__ dt_bias,
    float* __restrict__ qo, float* __restrict__ ko, float* __restrict__ vo,
    float* __restrict__ go, float* __restrict__ bo)
{
    const int l = blockIdx.x;
    const int tid = threadIdx.x;
    __shared__ float buf[8192];
    __shared__ float inv[32];

    for (int f = tid; f < 8192; f += 256) {
        int col;
        if (f < 2048) {
            col = (f >> 7) * 768 + (f & 127);
        } else if (f < 4096) {
            int ff = f - 2048;
            col = (ff >> 7) * 768 + 128 + (ff & 127);
        } else {
            int ff = f - 4096;
            int hv = ff >> 7;
            col = (hv >> 1) * 768 + 256 + (hv & 1) * 128 + (ff & 127);
        }
        float4 w4 = *(const float4*)(conv_w + (size_t)f * 4);
        const float* pc = proj + col;
        float s;
        if (l >= 3) {
            s = w4.x * pc[(size_t)(l - 3) * NPROJ]
              + w4.y * pc[(size_t)(l - 2) * NPROJ]
              + w4.z * pc[(size_t)(l - 1) * NPROJ]
              + w4.w * pc[(size_t)l       * NPROJ];
        } else {
            s = w4.w * pc[(size_t)l * NPROJ];
            if (l >= 1) s += w4.z * pc[(size_t)(l - 1) * NPROJ];
            if (l >= 2) s += w4.y * pc[(size_t)(l - 2) * NPROJ];
        }
        s = s / (1.f + __expf(-s));
        buf[f] = s;
    }
    __syncthreads();

    {
        int grp = tid >> 3, sub = tid & 7;
        int base = (grp < 16) ? grp * 128 : 2048 + (grp - 16) * 128;
        float ss = 0.f;
#pragma unroll
        for (int i = 0; i < 16; i++) {
            float x = buf[base + sub * 16 + i];
            ss += x * x;
        }
        ss += __shfl_xor_sync(0xffffffffu, ss, 4);
        ss += __shfl_xor_sync(0xffffffffu, ss, 2);
        ss += __shfl_xor_sync(0xffffffffu, ss, 1);
        if (sub == 0) inv[grp] = rsqrtf(ss + 1e-6f);
    }
    __syncthreads();

    const float qscale = 0.08838834764831845f;  // 128^-0.5
    for (int f = tid; f < 2048; f += 256) {
        qo[(size_t)l * 2048 + f] = buf[f]        * inv[f >> 7] * qscale;
        ko[(size_t)l * 2048 + f] = buf[2048 + f] * inv[16 + (f >> 7)];
    }
    for (int f = tid; f < 4096; f += 256)
        vo[(size_t)l * 4096 + f] = buf[4096 + f];

    if (tid < 32) {
        const float* prow = proj + (size_t)l * NPROJ;
        int hv = tid, hk = hv >> 1, gg = hv & 1;
        float bb = prow[QKVZ_N + hk * 4 + gg];
        float aa = prow[QKVZ_N + hk * 4 + 2 + gg];
        bo[(size_t)l * 32 + hv] = 1.f / (1.f + __expf(-bb));
        float x = aa + dt_bias[hv];
        float sp = (x > 20.f) ? x : log1pf(__expf(x));
        // store exp(g) directly (g <= 0 so this is in (0,1])
        go[(size_t)l * 32 + hv] = __expf(-__expf(A_log[hv]) * sp);
    }
}

// ---------------- warp-autonomous delta-rule scan (fine split) -----------------
// One warp per (hv, 4-column dv quad): 32 hv * 32 quads = 1024 warps, 256 CTAs,
// ~2 CTAs/SM so 2 warps share each SMSP and hide each other's stalls.
// lane = dks*4 + dvi (8 dk-slices of 16, 4 dv cols). Each lane holds S[16].
// Private 8-stage cp.async smem ring per warp; branch-free predicated scalar
// staging; exp(g) precomputed in prep. Reductions: butterfly xor 4, 8, 16.
// k/q slice-interleaved layout: store (lane&3)*128 + (lane>>2)*16; read
// j*128 + dks*16 -> 8 distinct 16B lines per 128B region, conflict-free.
#define SNS 8
#define SSTRIDE_B 1056      // k 512 | q 512 | v 16 | eg 4 | b 4 | pad 8

__global__ __launch_bounds__(128) void scan_kernel(
    const float* __restrict__ q, const float* __restrict__ k,
    const float* __restrict__ v, const float* __restrict__ eg_,
    const float* __restrict__ beta, float* __restrict__ core)
{
    __shared__ char ring[4][SNS][SSTRIDE_B];

    const int w = threadIdx.x >> 5;
    const int wglob = blockIdx.x * 4 + w;                 // 0..1023
    const int hv = wglob >> 5;
    const int quad = wglob & 31;
    const int hk = hv >> 1;
    const int lane = threadIdx.x & 31;
    const int dks = lane >> 2;     // dk slice 0..7 (16 elems each)
    const int dvi = lane & 3;

    const float* kp = k + (size_t)hk * DKC;               // + t*KEY_DIM
    const float* qp = q + (size_t)hk * DKC;
    const float* vp = v + (size_t)hv * DVC + quad * 4;    // + t*VAL_DIM
    const float* gp = eg_ + hv;                           // + t*NHV
    const float* bp = beta + hv;
    float* op = core + (size_t)hv * DVC + quad * 4 + dvi;
    const int wl = (dks == 0);

    const uint32_t rbase = smem_u32(&ring[w][0][0]);
    const uint32_t koff = (uint32_t)(((lane & 3) << 7) | ((lane >> 2) << 4));
    const uint32_t sc_active = (lane < 6) ? 1u : 0u;

    float S[16];
#pragma unroll
    for (int i = 0; i < 16; i++) S[i] = 0.f;

    // prologue: fill all 8 stages (t = 0..7)
#pragma unroll
    for (int s = 0; s < SNS; s++) {
        const uint32_t st = rbase + s * SSTRIDE_B;
        const size_t t = s;
        cpa16(st + koff,       kp + t * KEY_DIM + lane * 4);
        cpa16(st + 512 + koff, qp + t * KEY_DIM + lane * 4);
        const float* sc = (lane < 4) ? vp + t * VAL_DIM + lane
                        : ((lane == 4) ? gp + t * NHV : bp + t * NHV);
        cpa4p(st + 1024 + lane * 4, sc, sc_active);
        cpa_commit();
    }

    int slot = 0;
    for (int t = 0; t < LSEQ; t++) {
        cpa_wait7();            // oldest group (this slot) has landed
        __syncwarp();

        const char* sp_ = &ring[w][slot][0];
        float4 kf[4], qf[4];
#pragma unroll
        for (int j = 0; j < 4; j++) {
            kf[j] = *(const float4*)(sp_ + j * 128 + dks * 16);
            qf[j] = *(const float4*)(sp_ + 512 + j * 128 + dks * 16);
        }
        const float vt = *(const float*)(sp_ + 1024 + dvi * 4);
        const float eg = *(const float*)(sp_ + 1040);
        const float bt = *(const float*)(sp_ + 1044);
        __syncwarp();           // all lanes done reading before refill

        // refill this slot with step t+8 (clamped; redundant loads at tail)
        {
            const size_t tn = (t + SNS < LSEQ) ? (size_t)(t + SNS) : (size_t)(LSEQ - 1);
            const uint32_t st = rbase + slot * SSTRIDE_B;
            cpa16(st + koff,       kp + tn * KEY_DIM + lane * 4);
            cpa16(st + 512 + koff, qp + tn * KEY_DIM + lane * 4);
            const float* sc = (lane < 4) ? vp + tn * VAL_DIM + lane
                            : ((lane == 4) ? gp + tn * NHV : bp + tn * NHV);
            cpa4p(st + 1024 + lane * 4, sc, sc_active);
            cpa_commit();
        }
        if (++slot == SNS) slot = 0;

        // kv = k . S (local slice) -> butterfly over 8 slices
        float a0 = 0.f, a1 = 0.f, a2 = 0.f, a3 = 0.f;
#pragma unroll
        for (int j = 0; j < 4; j++) {
            a0 += kf[j].x * S[4 * j];
            a1 += kf[j].y * S[4 * j + 1];
            a2 += kf[j].z * S[4 * j + 2];
            a3 += kf[j].w * S[4 * j + 3];
        }
        float kv = (a0 + a1) + (a2 + a3);
        kv += __shfl_xor_sync(0xffffffffu, kv, 4);
        kv += __shfl_xor_sync(0xffffffffu, kv, 8);
        kv += __shfl_xor_sync(0xffffffffu, kv, 16);

        const float delta = (vt - eg * kv) * bt;

        float o0 = 0.f, o1 = 0.f, o2 = 0.f, o3 = 0.f;
#pragma unroll
        for (int j = 0; j < 4; j++) {
            S[4 * j]     = eg * S[4 * j]     + kf[j].x * delta;
            o0 += qf[j].x * S[4 * j];
            S[4 * j + 1] = eg * S[4 * j + 1] + kf[j].y * delta;
            o1 += qf[j].y * S[4 * j + 1];
            S[4 * j + 2] = eg * S[4 * j + 2] + kf[j].z * delta;
            o2 += qf[j].z * S[4 * j + 2];
            S[4 * j + 3] = eg * S[4 * j + 3] + kf[j].w * delta;
            o3 += qf[j].w * S[4 * j + 3];
        }
        float o = (o0 + o1) + (o2 + o3);
        o += __shfl_xor_sync(0xffffffffu, o, 4);
        o += __shfl_xor_sync(0xffffffffu, o, 8);
        o += __shfl_xor_sync(0xffffffffu, o, 16);
        if (wl) op[(size_t)t * VAL_DIM] = o;
    }
}

// ---------------- RMS-ish norm + silu(z) gate -> hi/lo bf16 -------------------
__global__ __launch_bounds__(128) void normgate_kernel(
    const float* __restrict__ core, const float* __restrict__ proj,
    const float* __restrict__ norm_w,
    __nv_bfloat16* __restrict__ ghi, __nv_bfloat16* __restrict__ glo)
{
    const int bx = blockIdx.x;          // l * 32 + hv
    const int l = bx >> 5;
    const int hv = bx & 31;
    const int d = threadIdx.x;

    float c = core[(size_t)bx * 128 + d];
    float ss = c * c;
#pragma unroll
    for (int o = 16; o > 0; o >>= 1)
        ss += __shfl_xor_sync(0xffffffffu, ss, o);
    __shared__ float r4[4];
    if ((d & 31) == 0) r4[d >> 5] = ss;
    __syncthreads();
    float var = (r4[0] + r4[1] + r4[2] + r4[3]) * (1.f / 128.f);

    int hk = hv >> 1, gg = hv & 1;
    float z = proj[(size_t)l * NPROJ + hk * 768 + 512 + gg * 128 + d];
    float sz = z / (1.f + __expf(-z));
    float val = c * rsqrtf(var + 1e-6f) * norm_w[d] * sz;

    __nv_bfloat16 h = __float2bfloat16(val);
    size_t idx = (size_t)bx * 128 + d;
    ghi[idx] = h;
    glo[idx] = __float2bfloat16(val - __bfloat162float(h));
}

// ---------------- launch ------------------------------------------------------
extern "C" void kernel_launch(void* const* d_in, const int* in_sizes, int n_in,
                              void* d_out, int out_size)
{
    const float* hidden     = (const float*)d_in[0];
    const float* in_proj_w  = (const float*)d_in[1];
    const float* conv_w     = (const float*)d_in[2];
    const float* A_log      = (const float*)d_in[3];
    const float* dt_bias    = (const float*)d_in[4];
    const float* norm_w     = (const float*)d_in[5];
    const float* out_proj_w = (const float*)d_in[6];
    float* out = (float*)d_out;

    float *p_proj, *p_q, *p_k, *p_v, *p_g, *p_b, *p_core;
    __nv_bfloat16 *p_hh, *p_hl, *p_w1h, *p_w1l, *p_gh, *p_gl, *p_w2h, *p_w2l;
    cudaGetSymbolAddress((void**)&p_proj, g_proj);
    cudaGetSymbolAddress((void**)&p_q,    g_q);
    cudaGetSymbolAddress((void**)&p_k,    g_k);
    cudaGetSymbolAddress((void**)&p_v,    g_v);
    cudaGetSymbolAddress((void**)&p_g,    g_gdec);
    cudaGetSymbolAddress((void**)&p_b,    g_beta);
    cudaGetSymbolAddress((void**)&p_core, g_core);
    cudaGetSymbolAddress((void**)&p_hh,   g_hid_hi);
    cudaGetSymbolAddress((void**)&p_hl,   g_hid_lo);
    cudaGetSymbolAddress((void**)&p_w1h,  g_w1_hi);
    cudaGetSymbolAddress((void**)&p_w1l,  g_w1_lo);
    cudaGetSymbolAddress((void**)&p_gh,   g_gat_hi);
    cudaGetSymbolAddress((void**)&p_gl,   g_gat_lo);
    cudaGetSymbolAddress((void**)&p_w2h,  g_w2_hi);
    cudaGetSymbolAddress((void**)&p_w2l,  g_w2_lo);

    cudaFuncSetAttribute(gemm_b3_kernel,
                         cudaFuncAttributeMaxDynamicSharedMemorySize, GEMM_SMEM);

    // operand conversions
    {
        size_t n = (size_t)LSEQ * HDIM;
        conv_hl_kernel<<<(unsigned)((n + 255) / 256), 256>>>(hidden, p_hh, p_hl, n);
    }
    convT_kernel<<<dim3(NPAD1 / 32, HDIM / 32), 256>>>(in_proj_w, p_w1h, p_w1l,
                                                       HDIM, NPROJ);
    convT_kernel<<<dim3(HDIM / 32, VAL_DIM / 32), 256>>>(out_proj_w, p_w2h, p_w2l,
                                                         VAL_DIM, HDIM);

    // 1) proj = hidden @ in_proj_w   (4096 x 12352, K=2048)
    gemm_b3_kernel<<<dim3(NPAD1 / 128, LSEQ / 128), 256, GEMM_SMEM>>>(
        p_hh, p_hl, p_w1h, p_w1l, p_proj, LSEQ, NPROJ, HDIM);

    // 2) conv + silu + l2norm + gate params (stores exp(g))
    prep_kernel<<<LSEQ, 256>>>(p_proj, conv_w, A_log, dt_bias,
                               p_q, p_k, p_v, p_g, p_b);

    // 3) warp-autonomous sequential scan (1024 warps, smem ring prefetch)
    scan_kernel<<<256, 128>>>(p_q, p_k, p_v, p_g, p_b, p_core);

    // 4) norm + gate -> bf16 hi/lo
    normgate_kernel<<<LSEQ * NHV, 128>>>(p_core, p_proj, norm_w, p_gh, p_gl);

    // 5) out = gated @ out_proj_w   (4096 x 2048, K=4096)
    gemm_b3_kernel<<<dim3(HDIM / 128, LSEQ / 128), 256, GEMM_SMEM>>>(
        p_gh, p_gl, p_w2h, p_w2l, out, LSEQ, HDIM, VAL_DIM);
}